// round 12
// baseline (speedup 1.0000x reference)
#include <cuda_runtime.h>
#include <cuda_fp16.h>
#include <math.h>
#include <stdint.h>

#define B_ 8
#define N_ 2048
#define H_ 1024
#define E_ 8
#define D_ 2048
#define T_ 16384   // B_*N_
#define TPAD_ (T_ + 1024)

// ---------------- scratch (device-side referenced ONLY from device code) ----------------
// Invariant: g_counts/g_prob_sum/g_entropy_sum/g_flag are ZERO on entry to every
// call (BSS for call 1; finalize resets). Pad rows of g_Xh are never written -> stay 0.
__device__ int    g_expert_idx[T_];
__device__ int    g_counts[E_];
__device__ int    g_offsets[E_ + 1];
__device__ int    g_poffsets[E_ + 1];
__device__ int    g_cursor[E_];
__device__ int    g_ptok[TPAD_];
__device__ float  g_prob_sum[E_];
__device__ float  g_entropy_sum;
__device__ volatile int g_flag;
__device__ __half g_Xh[(size_t)TPAD_ * H_];      // gathered tokens, fp16, padded per expert
__device__ __half g_Hh[(size_t)TPAD_ * D_];      // GELU activations, fp16

// ---------------- helpers ----------------
__device__ __forceinline__ uint32_t smem_u32(const void* p) {
    uint32_t a;
    asm("{ .reg .u64 t; cvta.to.shared.u64 t, %1; cvt.u32.u64 %0, t; }" : "=r"(a) : "l"(p));
    return a;
}
__device__ __forceinline__ void cp_async16(uint32_t dst, const void* src) {
    asm volatile("cp.async.cg.shared.global [%0], [%1], 16;" :: "r"(dst), "l"(src));
}
#define CP_COMMIT() asm volatile("cp.async.commit_group;" ::: "memory")
#define CP_WAIT1()  asm volatile("cp.async.wait_group 1;" ::: "memory")
#define CP_WAIT0()  asm volatile("cp.async.wait_group 0;" ::: "memory")

__device__ __forceinline__ void ldmatrix_x4(uint32_t& r0, uint32_t& r1,
                                            uint32_t& r2, uint32_t& r3, uint32_t addr) {
    asm volatile("ldmatrix.sync.aligned.m8n8.x4.shared.b16 {%0,%1,%2,%3}, [%4];"
                 : "=r"(r0), "=r"(r1), "=r"(r2), "=r"(r3) : "r"(addr));
}
__device__ __forceinline__ uint32_t pack_h2(float lo, float hi) {
    __half2 h = __floats2half2_rn(lo, hi);
    return *reinterpret_cast<uint32_t*>(&h);
}
__device__ __forceinline__ void mma_f16_16x8x16(float& d0, float& d1, float& d2, float& d3,
                                                uint32_t a0, uint32_t a1, uint32_t a2, uint32_t a3,
                                                uint32_t b0, uint32_t b1) {
    asm volatile(
        "mma.sync.aligned.m16n8k16.row.col.f32.f16.f16.f32 "
        "{%0,%1,%2,%3}, {%4,%5,%6,%7}, {%8,%9}, {%0,%1,%2,%3};"
        : "+f"(d0), "+f"(d1), "+f"(d2), "+f"(d3)
        : "r"(a0), "r"(a1), "r"(a2), "r"(a3), "r"(b0), "r"(b1));
}

// ---------------- router ----------------
__global__ void router_kernel(const float* __restrict__ x,
                              const float* __restrict__ Wr,
                              const float* __restrict__ br) {
    __shared__ float sWr[H_ * E_];
    for (int i = threadIdx.x; i < H_ * E_; i += blockDim.x) sWr[i] = Wr[i];
    __syncthreads();

    int warp = threadIdx.x >> 5;
    int lane = threadIdx.x & 31;
    int t = blockIdx.x * 8 + warp;
    if (t >= T_) return;

    const float* xr = x + (size_t)t * H_;
    float acc[E_];
#pragma unroll
    for (int e = 0; e < E_; e++) acc[e] = 0.f;
    for (int h = lane; h < H_; h += 32) {
        float xv = xr[h];
        const float* w = &sWr[h * E_];
#pragma unroll
        for (int e = 0; e < E_; e++) acc[e] += xv * w[e];
    }
#pragma unroll
    for (int e = 0; e < E_; e++) {
#pragma unroll
        for (int o = 16; o > 0; o >>= 1)
            acc[e] += __shfl_xor_sync(0xffffffffu, acc[e], o);
    }
    if (lane == 0) {
        float lg[E_];
        float mx = -1e30f;
        int arg = 0;
#pragma unroll
        for (int e = 0; e < E_; e++) {
            lg[e] = acc[e] + br[e];
            if (lg[e] > mx) { mx = lg[e]; arg = e; }
        }
        float s = 0.f;
#pragma unroll
        for (int e = 0; e < E_; e++) { lg[e] = expf(lg[e] - mx); s += lg[e]; }
        float inv = 1.f / s;
        float ent = 0.f;
#pragma unroll
        for (int e = 0; e < E_; e++) {
            float p = lg[e] * inv;
            atomicAdd(&g_prob_sum[e], p);
            ent -= p * logf(p + 1e-8f);
        }
        atomicAdd(&g_entropy_sum, ent);
        atomicAdd(&g_counts[arg], 1);
        g_expert_idx[t] = arg;
    }
}

// ---------------- scan + scatter + gather-to-fp16 (block per token) ----------------
__global__ void scanscatter_kernel(const float* __restrict__ x) {
    __shared__ int sp;
    const int t = blockIdx.x;
    if (threadIdx.x == 0) {
        if (t == 0) {
            int o = 0, po = 0;
            for (int e = 0; e < E_; e++) {
                g_offsets[e] = o;
                g_cursor[e] = o;
                g_poffsets[e] = po;
                o += g_counts[e];
                po += (g_counts[e] + 127) & ~127;
            }
            g_offsets[E_] = o;
            g_poffsets[E_] = po;
            __threadfence();
            g_flag = 1;
        } else {
            while (g_flag == 0) __nanosleep(64);
        }
        __threadfence();
        int e = g_expert_idx[t];
        int pos = atomicAdd(&g_cursor[e], 1);
        int p = g_poffsets[e] + (pos - g_offsets[e]);
        g_ptok[p] = t;
        sp = p;
    }
    __syncthreads();

    // block 0: mark pad slots (-1). Disjoint from real writes; GEMMs run after this kernel.
    if (t == 0) {
#pragma unroll
        for (int e = 0; e < E_; e++) {
            int start = g_poffsets[e] + g_counts[e];
            int end = g_poffsets[e + 1];
            for (int p = start + threadIdx.x; p < end; p += blockDim.x)
                g_ptok[p] = -1;
        }
    }

    const int p = sp;
    const float4* src = reinterpret_cast<const float4*>(x + (size_t)t * H_);
    __half2* dst = reinterpret_cast<__half2*>(g_Xh + (size_t)p * H_);
    for (int i = threadIdx.x; i < H_ / 4; i += blockDim.x) {
        float4 v = src[i];
        dst[i * 2 + 0] = __floats2half2_rn(v.x, v.y);
        dst[i * 2 + 1] = __floats2half2_rn(v.z, v.w);
    }
}

// ---------------- fp16-A / fp32-B-direct mma grouped GEMM ----------------
// R9/R10 shape: block 128x128, 256 threads, warp grid 2(M) x 4(N), warp tile 64x32
// (acc = 64 regs -> 2 CTAs/SM).  KC=32, 3-stage cp.async pipeline.
// A: fp16 (g_Xh / g_Hh), SMEM [128][40] halfs, frags via ldmatrix.x4.
// B: fp32 DIRECT from W[e][k][n] (no conversion pre-pass), SMEM [32][132] floats,
//    frags via 4 conflict-free LDS.32 + __floats2half2_rn (bit-identical; proven in R11).
#define STAGES  3
#define KC      32
#define PADA    40                          // halfs per A row
#define PADBF   132                         // floats per B row (128 + 4)
#define A_BYTES (128 * PADA * 2)            // 10240
#define B_BYTES (KC * PADBF * 4)            // 16896
#define STAGE_BYTES (A_BYTES + B_BYTES)     // 27136
#define GEMM_SMEM (STAGES * STAGE_BYTES)    // 81408

template<int KTOT, int NTOT, bool GELU>
__global__ void __launch_bounds__(256, 2)
moe_gemm(const float* __restrict__ xres,    // x (residual, GEMM2)
         const float* __restrict__ W,       // W1/W2 fp32: [E][KTOT][NTOT], N contiguous
         const float* __restrict__ bias,
         float* __restrict__ outp)
{
    constexpr int CCH = KTOT / KC;
    const __half* A = GELU ? g_Xh : g_Hh;

    const int e = blockIdx.z;
    const int pbase = g_poffsets[e];
    const int pcount = g_poffsets[e + 1] - pbase;
    const int m0 = blockIdx.y * 128;
    if (m0 >= pcount) return;
    const int n0 = blockIdx.x * 128;

    extern __shared__ char smc[];
    const uint32_t smbase = smem_u32(smc);

    const int tid = threadIdx.x;
    const int wid = tid >> 5;
    const int lane = tid & 31;
    const int grp = lane >> 2;     // 0..7
    const int qid = lane & 3;      // 0..3
    const int mrow = (wid & 1) * 64;
    const int nrow = (wid >> 1) * 32;

    // cp.async A: 2 x 16B per thread (512 chunks: row=idx>>2, c=idx&3)
    const char* aptr[2];
    uint32_t aoff[2];
#pragma unroll
    for (int i = 0; i < 2; i++) {
        int idx = tid + i * 256;
        int row = idx >> 2, c = idx & 3;
        aptr[i] = reinterpret_cast<const char*>(
                      A + (size_t)(pbase + m0 + row) * KTOT) + c * 16;
        aoff[i] = (uint32_t)(row * PADA + c * 8) * 2;
    }
    // cp.async B (fp32): 4 x 16B per thread (1024 chunks: kr=idx>>5, c=idx&31)
    const char* bptr[4];
    uint32_t boff[4];
#pragma unroll
    for (int i = 0; i < 4; i++) {
        int idx = tid + i * 256;
        int kr = idx >> 5, c = idx & 31;
        bptr[i] = reinterpret_cast<const char*>(
                      W + (size_t)e * KTOT * NTOT + (size_t)kr * NTOT + n0) + c * 16;
        boff[i] = (uint32_t)A_BYTES + (uint32_t)(kr * PADBF + c * 4) * 4;
    }

#define LOAD_STAGE(st, ch) do {                                                     \
        uint32_t _sb = smbase + (uint32_t)(st) * STAGE_BYTES;                       \
        size_t _ga = (size_t)(ch) * (KC * 2);                                       \
        size_t _gb = (size_t)(ch) * ((size_t)KC * NTOT * 4);                        \
        _Pragma("unroll")                                                           \
        for (int _i = 0; _i < 2; _i++) cp_async16(_sb + aoff[_i], aptr[_i] + _ga);  \
        _Pragma("unroll")                                                           \
        for (int _i = 0; _i < 4; _i++) cp_async16(_sb + boff[_i], bptr[_i] + _gb);  \
    } while (0)

    const uint32_t aFragBase =
        ((uint32_t)((mrow + (lane & 15)) * PADA + (lane >> 4) * 8)) * 2;

    float acc[4][4][4];
#pragma unroll
    for (int i = 0; i < 4; i++)
#pragma unroll
        for (int j = 0; j < 4; j++)
#pragma unroll
            for (int q = 0; q < 4; q++) acc[i][j][q] = 0.f;

    LOAD_STAGE(0, 0); CP_COMMIT();
    LOAD_STAGE(1, 1); CP_COMMIT();

    for (int c = 0; c < CCH; c++) {
        CP_WAIT1();
        __syncthreads();
        if (c + 2 < CCH) LOAD_STAGE((c + 2) % STAGES, c + 2);
        CP_COMMIT();

        const uint32_t stage = smbase + (uint32_t)(c % STAGES) * STAGE_BYTES;
        const float* BsF = reinterpret_cast<const float*>(
            smc + (size_t)(c % STAGES) * STAGE_BYTES + A_BYTES);

#pragma unroll
        for (int ks = 0; ks < 2; ks++) {
            uint32_t a[4][4], b[4][2];
#pragma unroll
            for (int fm = 0; fm < 4; fm++)
                ldmatrix_x4(a[fm][0], a[fm][1], a[fm][2], a[fm][3],
                            stage + aFragBase + fm * (16 * PADA * 2) + ks * 32);
            // B frags from fp32 SMEM (mapping proven in R11):
            // b0 = {B[2q][n], B[2q+1][n]},  b1 = {B[2q+8][n], B[2q+9][n]},  n = nrow+fn*8+grp
#pragma unroll
            for (int fn = 0; fn < 4; fn++) {
                const float* bp = BsF + (ks * 16 + 2 * qid) * PADBF + nrow + fn * 8 + grp;
                b[fn][0] = pack_h2(bp[0],         bp[PADBF]);
                b[fn][1] = pack_h2(bp[8 * PADBF], bp[9 * PADBF]);
            }
#pragma unroll
            for (int fm = 0; fm < 4; fm++)
#pragma unroll
                for (int fn = 0; fn < 4; fn++)
                    mma_f16_16x8x16(acc[fm][fn][0], acc[fm][fn][1],
                                    acc[fm][fn][2], acc[fm][fn][3],
                                    a[fm][0], a[fm][1], a[fm][2], a[fm][3],
                                    b[fn][0], b[fn][1]);
        }
    }
    CP_WAIT0();

    // ---- epilogue ----
    int toks[4][2];
    if (!GELU) {
#pragma unroll
        for (int fm = 0; fm < 4; fm++) {
            toks[fm][0] = g_ptok[pbase + m0 + mrow + fm * 16 + grp];
            toks[fm][1] = g_ptok[pbase + m0 + mrow + fm * 16 + grp + 8];
        }
    }

#pragma unroll
    for (int fn = 0; fn < 4; fn++) {
        const int col = n0 + nrow + fn * 8 + qid * 2;
        const float2 bv = *reinterpret_cast<const float2*>(bias + (size_t)e * NTOT + col);
#pragma unroll
        for (int fm = 0; fm < 4; fm++) {
#pragma unroll
            for (int h = 0; h < 2; h++) {
                float v0 = acc[fm][fn][h * 2 + 0] + bv.x;
                float v1 = acc[fm][fn][h * 2 + 1] + bv.y;
                if (GELU) {
                    const int prow = pbase + m0 + mrow + fm * 16 + grp + h * 8;
                    v0 = 0.5f * v0 * (1.0f + erff(v0 * 0.7071067811865476f));
                    v1 = 0.5f * v1 * (1.0f + erff(v1 * 0.7071067811865476f));
                    *reinterpret_cast<__half2*>(g_Hh + (size_t)prow * NTOT + col) =
                        __floats2half2_rn(v0, v1);
                } else {
                    const int tok = toks[fm][h];
                    if (tok >= 0) {
                        const float2 xr = *reinterpret_cast<const float2*>(
                            xres + (size_t)tok * NTOT + col);
                        *reinterpret_cast<float2*>(outp + (size_t)tok * NTOT + col) =
                            make_float2(v0 + xr.x, v1 + xr.y);
                    }
                }
            }
        }
    }
#undef LOAD_STAGE
}

// ---------------- losses + state reset for next call ----------------
__global__ void finalize_kernel(float* __restrict__ out, int out_size) {
    if (threadIdx.x == 0) {
        long long base = (long long)T_ * H_;
        if ((long long)out_size >= base + 2) {
            float s = 0.f;
            for (int e = 0; e < E_; e++) {
                float p = g_prob_sum[e] / (float)T_;
                s += p * p;
            }
            out[base] = (float)E_ * s;
            out[base + 1] = g_entropy_sum / (float)T_;
        }
        if ((long long)out_size >= base + 2 + E_) {
            for (int e = 0; e < E_; e++)
                out[base + 2 + e] = (float)g_counts[e];
        }
        for (int e = 0; e < E_; e++) { g_counts[e] = 0; g_prob_sum[e] = 0.f; }
        g_entropy_sum = 0.f;
        g_flag = 0;
    }
}

// ---------------- launch ----------------
extern "C" void kernel_launch(void* const* d_in, const int* in_sizes, int n_in,
                              void* d_out, int out_size) {
    const float* x  = (const float*)d_in[0];
    const float* Wr = (const float*)d_in[1];
    const float* br = (const float*)d_in[2];
    const float* W1 = (const float*)d_in[3];
    const float* b1 = (const float*)d_in[4];
    const float* W2 = (const float*)d_in[5];
    const float* b2 = (const float*)d_in[6];
    float* out = (float*)d_out;

    cudaFuncSetAttribute(moe_gemm<H_, D_, true>,
                         cudaFuncAttributeMaxDynamicSharedMemorySize, GEMM_SMEM);
    cudaFuncSetAttribute(moe_gemm<D_, H_, false>,
                         cudaFuncAttributeMaxDynamicSharedMemorySize, GEMM_SMEM);

    router_kernel<<<T_ / 8, 256>>>(x, Wr, br);                 // idx 0 (no W convert!)
    scanscatter_kernel<<<T_, 128>>>(x);                        // idx 1
    moe_gemm<H_, D_, true ><<<dim3(D_ / 128, T_ / 128, E_), 256, GEMM_SMEM>>>(x, W1, b1, out); // idx 2
    // idx 3 — the slot ncu captures:
    moe_gemm<D_, H_, false><<<dim3(H_ / 128, T_ / 128, E_), 256, GEMM_SMEM>>>(x, W2, b2, out); // idx 3
    finalize_kernel<<<1, 32>>>(out, out_size);                 // idx 4
}

// round 13
// speedup vs baseline: 1.1228x; 1.1228x over previous
#include <cuda_runtime.h>
#include <cuda_fp16.h>
#include <math.h>
#include <stdint.h>

#define B_ 8
#define N_ 2048
#define H_ 1024
#define E_ 8
#define D_ 2048
#define T_ 16384   // B_*N_
#define TPAD_ (T_ + 1024)

// ---------------- scratch (device-side referenced ONLY from device code) ----------------
// Invariant: g_counts/g_prob_sum/g_entropy_sum/g_flag are ZERO on entry to every
// call (BSS for call 1; finalize resets). Pad rows of g_Xh are never written -> stay 0.
__device__ int    g_expert_idx[T_];
__device__ int    g_counts[E_];
__device__ int    g_offsets[E_ + 1];
__device__ int    g_poffsets[E_ + 1];
__device__ int    g_cursor[E_];
__device__ int    g_ptok[TPAD_];
__device__ float  g_prob_sum[E_];
__device__ float  g_entropy_sum;
__device__ volatile int g_flag;
__device__ __half g_Xh[(size_t)TPAD_ * H_];      // gathered tokens, fp16, padded per expert
__device__ __half g_Hh[(size_t)TPAD_ * D_];      // GELU activations, fp16
__device__ __half g_W1h[(size_t)E_ * H_ * D_];   // W1 fp16
__device__ __half g_W2h[(size_t)E_ * D_ * H_];   // W2 fp16

// ---------------- helpers ----------------
__device__ __forceinline__ uint32_t smem_u32(const void* p) {
    uint32_t a;
    asm("{ .reg .u64 t; cvta.to.shared.u64 t, %1; cvt.u32.u64 %0, t; }" : "=r"(a) : "l"(p));
    return a;
}
__device__ __forceinline__ void cp_async16(uint32_t dst, const void* src) {
    asm volatile("cp.async.cg.shared.global [%0], [%1], 16;" :: "r"(dst), "l"(src));
}
#define CP_COMMIT() asm volatile("cp.async.commit_group;" ::: "memory")
#define CP_WAIT1()  asm volatile("cp.async.wait_group 1;" ::: "memory")
#define CP_WAIT0()  asm volatile("cp.async.wait_group 0;" ::: "memory")

__device__ __forceinline__ void ldmatrix_x4(uint32_t& r0, uint32_t& r1,
                                            uint32_t& r2, uint32_t& r3, uint32_t addr) {
    asm volatile("ldmatrix.sync.aligned.m8n8.x4.shared.b16 {%0,%1,%2,%3}, [%4];"
                 : "=r"(r0), "=r"(r1), "=r"(r2), "=r"(r3) : "r"(addr));
}
__device__ __forceinline__ void ldmatrix_x2t(uint32_t& r0, uint32_t& r1, uint32_t addr) {
    asm volatile("ldmatrix.sync.aligned.m8n8.x2.trans.shared.b16 {%0,%1}, [%2];"
                 : "=r"(r0), "=r"(r1) : "r"(addr));
}
__device__ __forceinline__ void mma_f16_16x8x16(float& d0, float& d1, float& d2, float& d3,
                                                uint32_t a0, uint32_t a1, uint32_t a2, uint32_t a3,
                                                uint32_t b0, uint32_t b1) {
    asm volatile(
        "mma.sync.aligned.m16n8k16.row.col.f32.f16.f16.f32 "
        "{%0,%1,%2,%3}, {%4,%5,%6,%7}, {%8,%9}, {%0,%1,%2,%3};"
        : "+f"(d0), "+f"(d1), "+f"(d2), "+f"(d3)
        : "r"(a0), "r"(a1), "r"(a2), "r"(a3), "r"(b0), "r"(b1));
}

// ---------------- W -> fp16 convert: dedicated streaming kernel ----------------
// 4096 blocks x 256 threads x 4 float4 = 16.78M floats = one full W tensor.
template<int WHICH>
__global__ void __launch_bounds__(256) wconv_kernel(const float* __restrict__ W) {
    __half2* d = reinterpret_cast<__half2*>(WHICH ? g_W2h : g_W1h);
    const float4* s = reinterpret_cast<const float4*>(W);
    const size_t gtid = (size_t)blockIdx.x * 256 + threadIdx.x;
#pragma unroll
    for (int i = 0; i < 4; i++) {
        size_t idx = gtid + (size_t)i * (4096 * 256);
        float4 v = s[idx];
        d[idx * 2 + 0] = __floats2half2_rn(v.x, v.y);
        d[idx * 2 + 1] = __floats2half2_rn(v.z, v.w);
    }
}

// ---------------- router ----------------
__global__ void router_kernel(const float* __restrict__ x,
                              const float* __restrict__ Wr,
                              const float* __restrict__ br) {
    __shared__ float sWr[H_ * E_];
    for (int i = threadIdx.x; i < H_ * E_; i += blockDim.x) sWr[i] = Wr[i];
    __syncthreads();

    int warp = threadIdx.x >> 5;
    int lane = threadIdx.x & 31;
    int t = blockIdx.x * 8 + warp;
    if (t >= T_) return;

    const float* xr = x + (size_t)t * H_;
    float acc[E_];
#pragma unroll
    for (int e = 0; e < E_; e++) acc[e] = 0.f;
    for (int h = lane; h < H_; h += 32) {
        float xv = xr[h];
        const float* w = &sWr[h * E_];
#pragma unroll
        for (int e = 0; e < E_; e++) acc[e] += xv * w[e];
    }
#pragma unroll
    for (int e = 0; e < E_; e++) {
#pragma unroll
        for (int o = 16; o > 0; o >>= 1)
            acc[e] += __shfl_xor_sync(0xffffffffu, acc[e], o);
    }
    if (lane == 0) {
        float lg[E_];
        float mx = -1e30f;
        int arg = 0;
#pragma unroll
        for (int e = 0; e < E_; e++) {
            lg[e] = acc[e] + br[e];
            if (lg[e] > mx) { mx = lg[e]; arg = e; }
        }
        float s = 0.f;
#pragma unroll
        for (int e = 0; e < E_; e++) { lg[e] = expf(lg[e] - mx); s += lg[e]; }
        float inv = 1.f / s;
        float ent = 0.f;
#pragma unroll
        for (int e = 0; e < E_; e++) {
            float p = lg[e] * inv;
            atomicAdd(&g_prob_sum[e], p);
            ent -= p * logf(p + 1e-8f);
        }
        atomicAdd(&g_entropy_sum, ent);
        atomicAdd(&g_counts[arg], 1);
        g_expert_idx[t] = arg;
    }
}

// ---------------- scan + scatter + gather-to-fp16 (block per token) ----------------
__global__ void scanscatter_kernel(const float* __restrict__ x) {
    __shared__ int sp;
    const int t = blockIdx.x;
    if (threadIdx.x == 0) {
        if (t == 0) {
            int o = 0, po = 0;
            for (int e = 0; e < E_; e++) {
                g_offsets[e] = o;
                g_cursor[e] = o;
                g_poffsets[e] = po;
                o += g_counts[e];
                po += (g_counts[e] + 127) & ~127;
            }
            g_offsets[E_] = o;
            g_poffsets[E_] = po;
            __threadfence();
            g_flag = 1;
        } else {
            while (g_flag == 0) __nanosleep(64);
        }
        __threadfence();
        int e = g_expert_idx[t];
        int pos = atomicAdd(&g_cursor[e], 1);
        int p = g_poffsets[e] + (pos - g_offsets[e]);
        g_ptok[p] = t;
        sp = p;
    }
    __syncthreads();

    // block 0: mark pad slots (-1). Disjoint from real writes; GEMMs run after this kernel.
    if (t == 0) {
#pragma unroll
        for (int e = 0; e < E_; e++) {
            int start = g_poffsets[e] + g_counts[e];
            int end = g_poffsets[e + 1];
            for (int p = start + threadIdx.x; p < end; p += blockDim.x)
                g_ptok[p] = -1;
        }
    }

    const int p = sp;
    const float4* src = reinterpret_cast<const float4*>(x + (size_t)t * H_);
    __half2* dst = reinterpret_cast<__half2*>(g_Xh + (size_t)p * H_);
    for (int i = threadIdx.x; i < H_ / 4; i += blockDim.x) {
        float4 v = src[i];
        dst[i * 2 + 0] = __floats2half2_rn(v.x, v.y);
        dst[i * 2 + 1] = __floats2half2_rn(v.z, v.w);
    }
}

// ---------------- fp16 mma grouped GEMM: 128x128 tile, 2 CTAs/SM (R9/R10, known best) ----------------
#define STAGES  3
#define KC      32
#define PADA    40                         // halfs per A row
#define PADB    136                        // halfs per B row (128 + 8)
#define A_HALFS (128 * PADA)               // 5120
#define B_HALFS (KC * PADB)                // 4352
#define STAGE_BYTES ((A_HALFS + B_HALFS) * 2)   // 18944
#define GEMM_SMEM (STAGES * STAGE_BYTES)        // 56832

template<int KTOT, int NTOT, bool GELU>
__global__ void __launch_bounds__(256, 2)
moe_gemm(const float* __restrict__ xres,   // x (residual, GEMM2)
         const float* __restrict__ bias,
         float* __restrict__ outp)
{
    constexpr int CCH = KTOT / KC;
    const __half* A  = GELU ? g_Xh  : g_Hh;
    const __half* Wh = GELU ? g_W1h : g_W2h;

    const int e = blockIdx.z;
    const int pbase = g_poffsets[e];
    const int pcount = g_poffsets[e + 1] - pbase;
    const int m0 = blockIdx.y * 128;
    if (m0 >= pcount) return;
    const int n0 = blockIdx.x * 128;

    extern __shared__ __half smh[];
    const uint32_t smbase = smem_u32(smh);

    const int tid = threadIdx.x;
    const int wid = tid >> 5;
    const int lane = tid & 31;
    const int grp = lane >> 2;     // 0..7
    const int qid = lane & 3;      // 0..3
    const int mrow = (wid & 1) * 64;
    const int nrow = (wid >> 1) * 32;

    // cp.async A: 2 x 16B per thread (512 chunks: row=idx>>2, c=idx&3)
    const char* aptr[2];
    uint32_t aoff[2];
#pragma unroll
    for (int i = 0; i < 2; i++) {
        int idx = tid + i * 256;
        int row = idx >> 2, c = idx & 3;
        aptr[i] = reinterpret_cast<const char*>(
                      A + (size_t)(pbase + m0 + row) * KTOT) + c * 16;
        aoff[i] = (uint32_t)(row * PADA + c * 8) * 2;
    }
    // cp.async B: 2 x 16B per thread (512 chunks: kr=idx>>4, c=idx&15)
    const char* bptr[2];
    uint32_t boff[2];
#pragma unroll
    for (int i = 0; i < 2; i++) {
        int idx = tid + i * 256;
        int kr = idx >> 4, c = idx & 15;
        bptr[i] = reinterpret_cast<const char*>(
                      Wh + (size_t)e * KTOT * NTOT + (size_t)kr * NTOT + n0) + c * 16;
        boff[i] = (uint32_t)(A_HALFS + kr * PADB + c * 8) * 2;
    }

#define LOAD_STAGE(st, ch) do {                                                     \
        uint32_t _sb = smbase + (uint32_t)(st) * STAGE_BYTES;                       \
        size_t _ga = (size_t)(ch) * (KC * 2);                                       \
        size_t _gb = (size_t)(ch) * ((size_t)KC * NTOT * 2);                        \
        _Pragma("unroll")                                                           \
        for (int _i = 0; _i < 2; _i++) cp_async16(_sb + aoff[_i], aptr[_i] + _ga);  \
        _Pragma("unroll")                                                           \
        for (int _i = 0; _i < 2; _i++) cp_async16(_sb + boff[_i], bptr[_i] + _gb);  \
    } while (0)

    const uint32_t aFragBase =
        ((uint32_t)((mrow + (lane & 15)) * PADA + (lane >> 4) * 8)) * 2;
    const uint32_t bFragBase =
        (uint32_t)(A_HALFS * 2) + ((uint32_t)((lane & 15) * PADB + nrow)) * 2;

    float acc[4][4][4];
#pragma unroll
    for (int i = 0; i < 4; i++)
#pragma unroll
        for (int j = 0; j < 4; j++)
#pragma unroll
            for (int q = 0; q < 4; q++) acc[i][j][q] = 0.f;

    LOAD_STAGE(0, 0); CP_COMMIT();
    LOAD_STAGE(1, 1); CP_COMMIT();

    for (int c = 0; c < CCH; c++) {
        CP_WAIT1();
        __syncthreads();
        if (c + 2 < CCH) LOAD_STAGE((c + 2) % STAGES, c + 2);
        CP_COMMIT();

        const uint32_t stage = smbase + (uint32_t)(c % STAGES) * STAGE_BYTES;

#pragma unroll
        for (int ks = 0; ks < 2; ks++) {
            uint32_t a[4][4], b[4][2];
#pragma unroll
            for (int fm = 0; fm < 4; fm++)
                ldmatrix_x4(a[fm][0], a[fm][1], a[fm][2], a[fm][3],
                            stage + aFragBase + fm * (16 * PADA * 2) + ks * 32);
#pragma unroll
            for (int fn = 0; fn < 4; fn++)
                ldmatrix_x2t(b[fn][0], b[fn][1],
                             stage + bFragBase + fn * 16 + ks * (16 * PADB * 2));
#pragma unroll
            for (int fm = 0; fm < 4; fm++)
#pragma unroll
                for (int fn = 0; fn < 4; fn++)
                    mma_f16_16x8x16(acc[fm][fn][0], acc[fm][fn][1],
                                    acc[fm][fn][2], acc[fm][fn][3],
                                    a[fm][0], a[fm][1], a[fm][2], a[fm][3],
                                    b[fn][0], b[fn][1]);
        }
    }
    CP_WAIT0();

    // ---- epilogue ----
    int toks[4][2];
    if (!GELU) {
#pragma unroll
        for (int fm = 0; fm < 4; fm++) {
            toks[fm][0] = g_ptok[pbase + m0 + mrow + fm * 16 + grp];
            toks[fm][1] = g_ptok[pbase + m0 + mrow + fm * 16 + grp + 8];
        }
    }

#pragma unroll
    for (int fn = 0; fn < 4; fn++) {
        const int col = n0 + nrow + fn * 8 + qid * 2;
        const float2 bv = *reinterpret_cast<const float2*>(bias + (size_t)e * NTOT + col);
#pragma unroll
        for (int fm = 0; fm < 4; fm++) {
#pragma unroll
            for (int h = 0; h < 2; h++) {
                float v0 = acc[fm][fn][h * 2 + 0] + bv.x;
                float v1 = acc[fm][fn][h * 2 + 1] + bv.y;
                if (GELU) {
                    const int prow = pbase + m0 + mrow + fm * 16 + grp + h * 8;
                    v0 = 0.5f * v0 * (1.0f + erff(v0 * 0.7071067811865476f));
                    v1 = 0.5f * v1 * (1.0f + erff(v1 * 0.7071067811865476f));
                    *reinterpret_cast<__half2*>(g_Hh + (size_t)prow * NTOT + col) =
                        __floats2half2_rn(v0, v1);
                } else {
                    const int tok = toks[fm][h];
                    if (tok >= 0) {
                        const float2 xr = *reinterpret_cast<const float2*>(
                            xres + (size_t)tok * NTOT + col);
                        *reinterpret_cast<float2*>(outp + (size_t)tok * NTOT + col) =
                            make_float2(v0 + xr.x, v1 + xr.y);
                    }
                }
            }
        }
    }
#undef LOAD_STAGE
}

// ---------------- losses + state reset for next call ----------------
__global__ void finalize_kernel(float* __restrict__ out, int out_size) {
    if (threadIdx.x == 0) {
        long long base = (long long)T_ * H_;
        if ((long long)out_size >= base + 2) {
            float s = 0.f;
            for (int e = 0; e < E_; e++) {
                float p = g_prob_sum[e] / (float)T_;
                s += p * p;
            }
            out[base] = (float)E_ * s;
            out[base + 1] = g_entropy_sum / (float)T_;
        }
        if ((long long)out_size >= base + 2 + E_) {
            for (int e = 0; e < E_; e++)
                out[base + 2 + e] = (float)g_counts[e];
        }
        for (int e = 0; e < E_; e++) { g_counts[e] = 0; g_prob_sum[e] = 0.f; }
        g_entropy_sum = 0.f;
        g_flag = 0;
    }
}

// ---------------- launch ----------------
extern "C" void kernel_launch(void* const* d_in, const int* in_sizes, int n_in,
                              void* d_out, int out_size) {
    const float* x  = (const float*)d_in[0];
    const float* Wr = (const float*)d_in[1];
    const float* br = (const float*)d_in[2];
    const float* W1 = (const float*)d_in[3];
    const float* b1 = (const float*)d_in[4];
    const float* W2 = (const float*)d_in[5];
    const float* b2 = (const float*)d_in[6];
    float* out = (float*)d_out;

    cudaFuncSetAttribute(moe_gemm<H_, D_, true>,
                         cudaFuncAttributeMaxDynamicSharedMemorySize, GEMM_SMEM);
    cudaFuncSetAttribute(moe_gemm<D_, H_, false>,
                         cudaFuncAttributeMaxDynamicSharedMemorySize, GEMM_SMEM);

    wconv_kernel<0><<<4096, 256>>>(W1);                        // idx 0
    router_kernel<<<T_ / 8, 256>>>(x, Wr, br);                 // idx 1
    scanscatter_kernel<<<T_, 128>>>(x);                        // idx 2
    wconv_kernel<1><<<4096, 256>>>(W2);                        // idx 3 <- profiled this round
    moe_gemm<H_, D_, true ><<<dim3(D_ / 128, T_ / 128, E_), 256, GEMM_SMEM>>>(x, b1, out); // idx 4
    moe_gemm<D_, H_, false><<<dim3(H_ / 128, T_ / 128, E_), 256, GEMM_SMEM>>>(x, b2, out); // idx 5
    finalize_kernel<<<1, 32>>>(out, out_size);                 // idx 6
}

// round 14
// speedup vs baseline: 1.4573x; 1.2979x over previous
#include <cuda_runtime.h>
#include <cuda_fp16.h>
#include <math.h>
#include <stdint.h>

#define B_ 8
#define N_ 2048
#define H_ 1024
#define E_ 8
#define D_ 2048
#define T_ 16384   // B_*N_
#define TPAD_ (T_ + 1024)

// ---------------- scratch (device-side referenced ONLY from device code) ----------------
// Invariant: g_counts/g_prob_sum/g_entropy_sum/g_flag are ZERO on entry to every
// call (BSS for call 1; finalize resets).
__device__ int    g_expert_idx[T_];
__device__ int    g_counts[E_];
__device__ int    g_offsets[E_ + 1];
__device__ int    g_poffsets[E_ + 1];
__device__ int    g_cursor[E_];
__device__ int    g_ptok[TPAD_];
__device__ float  g_prob_sum[E_];
__device__ float  g_entropy_sum;
__device__ volatile int g_flag;
__device__ __half g_Xh[(size_t)TPAD_ * H_];      // gathered tokens, fp16, padded per expert
__device__ __half g_Hh[(size_t)TPAD_ * D_];      // GELU activations, fp16
__device__ __half g_W1h[(size_t)E_ * H_ * D_];   // W1 fp16
__device__ __half g_W2h[(size_t)E_ * D_ * H_];   // W2 fp16

// ---------------- helpers ----------------
__device__ __forceinline__ uint32_t smem_u32(const void* p) {
    uint32_t a;
    asm("{ .reg .u64 t; cvta.to.shared.u64 t, %1; cvt.u32.u64 %0, t; }" : "=r"(a) : "l"(p));
    return a;
}
__device__ __forceinline__ void cp_async16(uint32_t dst, const void* src) {
    asm volatile("cp.async.cg.shared.global [%0], [%1], 16;" :: "r"(dst), "l"(src));
}
#define CP_COMMIT() asm volatile("cp.async.commit_group;" ::: "memory")
#define CP_WAIT1()  asm volatile("cp.async.wait_group 1;" ::: "memory")
#define CP_WAIT0()  asm volatile("cp.async.wait_group 0;" ::: "memory")

__device__ __forceinline__ void ldmatrix_x4(uint32_t& r0, uint32_t& r1,
                                            uint32_t& r2, uint32_t& r3, uint32_t addr) {
    asm volatile("ldmatrix.sync.aligned.m8n8.x4.shared.b16 {%0,%1,%2,%3}, [%4];"
                 : "=r"(r0), "=r"(r1), "=r"(r2), "=r"(r3) : "r"(addr));
}
__device__ __forceinline__ void ldmatrix_x2t(uint32_t& r0, uint32_t& r1, uint32_t addr) {
    asm volatile("ldmatrix.sync.aligned.m8n8.x2.trans.shared.b16 {%0,%1}, [%2];"
                 : "=r"(r0), "=r"(r1) : "r"(addr));
}
__device__ __forceinline__ void mma_f16_16x8x16(float& d0, float& d1, float& d2, float& d3,
                                                uint32_t a0, uint32_t a1, uint32_t a2, uint32_t a3,
                                                uint32_t b0, uint32_t b1) {
    asm volatile(
        "mma.sync.aligned.m16n8k16.row.col.f32.f16.f16.f32 "
        "{%0,%1,%2,%3}, {%4,%5,%6,%7}, {%8,%9}, {%0,%1,%2,%3};"
        : "+f"(d0), "+f"(d1), "+f"(d2), "+f"(d3)
        : "r"(a0), "r"(a1), "r"(a2), "r"(a3), "r"(b0), "r"(b1));
}

// ---------------- W -> fp16 convert (streaming) ----------------
// WHICH 0/1 : halves of W1;  WHICH 2 : all of W2.
template<int WHICH>
__global__ void __launch_bounds__(256) wconv_kernel(const float* __restrict__ W) {
    __half2* d = reinterpret_cast<__half2*>(WHICH == 2 ? g_W2h
                                                       : g_W1h + (WHICH ? (size_t)E_ * H_ * D_ / 2 : 0));
    const float4* s = reinterpret_cast<const float4*>(
        WHICH == 1 ? W + (size_t)E_ * H_ * D_ / 2 : W);
    const int iters = (WHICH == 2) ? 4 : 2;
    const size_t gtid = (size_t)blockIdx.x * 256 + threadIdx.x;
    for (int i = 0; i < iters; i++) {
        size_t idx = gtid + (size_t)i * (4096 * 256);
        float4 v = s[idx];
        d[idx * 2 + 0] = __floats2half2_rn(v.x, v.y);
        d[idx * 2 + 1] = __floats2half2_rn(v.z, v.w);
    }
}

// ---------------- router: 1024 thr/block, block-level loss reduction ----------------
__global__ void __launch_bounds__(1024) router_kernel(const float* __restrict__ x,
                                                      const float* __restrict__ Wr,
                                                      const float* __restrict__ br) {
    __shared__ float sWr[H_ * E_];           // 32 KB
    __shared__ float s_prob[E_];
    __shared__ float s_ent;
    __shared__ int   s_cnt[E_];
    if (threadIdx.x < E_) { s_prob[threadIdx.x] = 0.f; s_cnt[threadIdx.x] = 0; }
    if (threadIdx.x == 0) s_ent = 0.f;
    for (int i = threadIdx.x; i < H_ * E_; i += blockDim.x) sWr[i] = Wr[i];
    __syncthreads();

    int warp = threadIdx.x >> 5;             // 0..31
    int lane = threadIdx.x & 31;
    int t = blockIdx.x * 32 + warp;

    const float* xr = x + (size_t)t * H_;
    float acc[E_];
#pragma unroll
    for (int e = 0; e < E_; e++) acc[e] = 0.f;
    for (int h = lane; h < H_; h += 32) {
        float xv = xr[h];
        const float* w = &sWr[h * E_];
#pragma unroll
        for (int e = 0; e < E_; e++) acc[e] += xv * w[e];
    }
#pragma unroll
    for (int e = 0; e < E_; e++) {
#pragma unroll
        for (int o = 16; o > 0; o >>= 1)
            acc[e] += __shfl_xor_sync(0xffffffffu, acc[e], o);
    }
    if (lane == 0) {
        float lg[E_];
        float mx = -1e30f;
        int arg = 0;
#pragma unroll
        for (int e = 0; e < E_; e++) {
            lg[e] = acc[e] + br[e];
            if (lg[e] > mx) { mx = lg[e]; arg = e; }
        }
        float s = 0.f;
#pragma unroll
        for (int e = 0; e < E_; e++) { lg[e] = expf(lg[e] - mx); s += lg[e]; }
        float inv = 1.f / s;
        float ent = 0.f;
#pragma unroll
        for (int e = 0; e < E_; e++) {
            float p = lg[e] * inv;
            atomicAdd(&s_prob[e], p);        // shared atomics: cheap
            ent -= p * logf(p + 1e-8f);
        }
        atomicAdd(&s_ent, ent);
        atomicAdd(&s_cnt[arg], 1);
        g_expert_idx[t] = arg;
    }
    __syncthreads();
    // one global atomic per quantity per block (512 blocks -> 512/address)
    if (threadIdx.x < E_) atomicAdd(&g_prob_sum[threadIdx.x], s_prob[threadIdx.x]);
    else if (threadIdx.x == E_) atomicAdd(&g_entropy_sum, s_ent);
    else if (threadIdx.x >= 16 && threadIdx.x < 16 + E_)
        atomicAdd(&g_counts[threadIdx.x - 16], s_cnt[threadIdx.x - 16]);
}

// ---------------- scatter: scan + warp-aggregated position assignment ----------------
__global__ void __launch_bounds__(256) scatter_kernel() {
    const int t = blockIdx.x * 256 + threadIdx.x;
    if (t == 0) {
        int o = 0, po = 0;
        for (int e = 0; e < E_; e++) {
            g_offsets[e] = o;
            g_cursor[e] = o;
            g_poffsets[e] = po;
            o += g_counts[e];
            po += (g_counts[e] + 127) & ~127;
        }
        g_offsets[E_] = o;
        g_poffsets[E_] = po;
        __threadfence();
        g_flag = 1;
    }
    // all threads (including block 0's) wait for the scan
    if (threadIdx.x == 0 && blockIdx.x != 0) {
        while (g_flag == 0) __nanosleep(64);
    }
    __syncthreads();
    __threadfence();

    const int e = g_expert_idx[t];
    // warp-aggregated atomic: one RMW per (warp, expert) group
    unsigned mask = __match_any_sync(0xffffffffu, e);
    int leader = __ffs(mask) - 1;
    int rank = __popc(mask & ((1u << (threadIdx.x & 31)) - 1));
    int base = 0;
    if ((threadIdx.x & 31) == leader)
        base = atomicAdd(&g_cursor[e], __popc(mask));
    base = __shfl_sync(0xffffffffu, base, leader);
    const int pos = base + rank;
    const int p = g_poffsets[e] + (pos - g_offsets[e]);
    g_ptok[p] = t;

    // block 0 additionally marks pad slots
    if (blockIdx.x == 0) {
        __syncthreads();
#pragma unroll
        for (int e2 = 0; e2 < E_; e2++) {
            int start = g_poffsets[e2] + g_counts[e2];
            int end = g_poffsets[e2 + 1];
            for (int q = start + threadIdx.x; q < end; q += 256)
                g_ptok[q] = -1;
        }
    }
}

// ---------------- gather: block per padded slot, fp16 convert ----------------
__global__ void __launch_bounds__(128) gather_kernel(const float* __restrict__ x) {
    const int p = blockIdx.x;
    if (p >= g_poffsets[E_]) return;
    const int tok = g_ptok[p];
    __half2* dst = reinterpret_cast<__half2*>(g_Xh + (size_t)p * H_);
    if (tok >= 0) {
        const float4* src = reinterpret_cast<const float4*>(x + (size_t)tok * H_);
        for (int i = threadIdx.x; i < H_ / 4; i += 128) {
            float4 v = src[i];
            dst[i * 2 + 0] = __floats2half2_rn(v.x, v.y);
            dst[i * 2 + 1] = __floats2half2_rn(v.z, v.w);
        }
    } else {
        const __half2 z = __floats2half2_rn(0.f, 0.f);
        for (int i = threadIdx.x; i < H_ / 4; i += 128) {
            dst[i * 2 + 0] = z;
            dst[i * 2 + 1] = z;
        }
    }
}

// ---------------- fp16 mma grouped GEMM: 128x128 tile, 2 CTAs/SM (R9/R10, frozen) ----------------
#define STAGES  3
#define KC      32
#define PADA    40                         // halfs per A row
#define PADB    136                        // halfs per B row (128 + 8)
#define A_HALFS (128 * PADA)               // 5120
#define B_HALFS (KC * PADB)                // 4352
#define STAGE_BYTES ((A_HALFS + B_HALFS) * 2)   // 18944
#define GEMM_SMEM (STAGES * STAGE_BYTES)        // 56832

template<int KTOT, int NTOT, bool GELU>
__global__ void __launch_bounds__(256, 2)
moe_gemm(const float* __restrict__ xres,   // x (residual, GEMM2)
         const float* __restrict__ bias,
         float* __restrict__ outp)
{
    constexpr int CCH = KTOT / KC;
    const __half* A  = GELU ? g_Xh  : g_Hh;
    const __half* Wh = GELU ? g_W1h : g_W2h;

    const int e = blockIdx.z;
    const int pbase = g_poffsets[e];
    const int pcount = g_poffsets[e + 1] - pbase;
    const int m0 = blockIdx.y * 128;
    if (m0 >= pcount) return;
    const int n0 = blockIdx.x * 128;

    extern __shared__ __half smh[];
    const uint32_t smbase = smem_u32(smh);

    const int tid = threadIdx.x;
    const int wid = tid >> 5;
    const int lane = tid & 31;
    const int grp = lane >> 2;
    const int qid = lane & 3;
    const int mrow = (wid & 1) * 64;
    const int nrow = (wid >> 1) * 32;

    const char* aptr[2];
    uint32_t aoff[2];
#pragma unroll
    for (int i = 0; i < 2; i++) {
        int idx = tid + i * 256;
        int row = idx >> 2, c = idx & 3;
        aptr[i] = reinterpret_cast<const char*>(
                      A + (size_t)(pbase + m0 + row) * KTOT) + c * 16;
        aoff[i] = (uint32_t)(row * PADA + c * 8) * 2;
    }
    const char* bptr[2];
    uint32_t boff[2];
#pragma unroll
    for (int i = 0; i < 2; i++) {
        int idx = tid + i * 256;
        int kr = idx >> 4, c = idx & 15;
        bptr[i] = reinterpret_cast<const char*>(
                      Wh + (size_t)e * KTOT * NTOT + (size_t)kr * NTOT + n0) + c * 16;
        boff[i] = (uint32_t)(A_HALFS + kr * PADB + c * 8) * 2;
    }

#define LOAD_STAGE(st, ch) do {                                                     \
        uint32_t _sb = smbase + (uint32_t)(st) * STAGE_BYTES;                       \
        size_t _ga = (size_t)(ch) * (KC * 2);                                       \
        size_t _gb = (size_t)(ch) * ((size_t)KC * NTOT * 2);                        \
        _Pragma("unroll")                                                           \
        for (int _i = 0; _i < 2; _i++) cp_async16(_sb + aoff[_i], aptr[_i] + _ga);  \
        _Pragma("unroll")                                                           \
        for (int _i = 0; _i < 2; _i++) cp_async16(_sb + boff[_i], bptr[_i] + _gb);  \
    } while (0)

    const uint32_t aFragBase =
        ((uint32_t)((mrow + (lane & 15)) * PADA + (lane >> 4) * 8)) * 2;
    const uint32_t bFragBase =
        (uint32_t)(A_HALFS * 2) + ((uint32_t)((lane & 15) * PADB + nrow)) * 2;

    float acc[4][4][4];
#pragma unroll
    for (int i = 0; i < 4; i++)
#pragma unroll
        for (int j = 0; j < 4; j++)
#pragma unroll
            for (int q = 0; q < 4; q++) acc[i][j][q] = 0.f;

    LOAD_STAGE(0, 0); CP_COMMIT();
    LOAD_STAGE(1, 1); CP_COMMIT();

    for (int c = 0; c < CCH; c++) {
        CP_WAIT1();
        __syncthreads();
        if (c + 2 < CCH) LOAD_STAGE((c + 2) % STAGES, c + 2);
        CP_COMMIT();

        const uint32_t stage = smbase + (uint32_t)(c % STAGES) * STAGE_BYTES;

#pragma unroll
        for (int ks = 0; ks < 2; ks++) {
            uint32_t a[4][4], b[4][2];
#pragma unroll
            for (int fm = 0; fm < 4; fm++)
                ldmatrix_x4(a[fm][0], a[fm][1], a[fm][2], a[fm][3],
                            stage + aFragBase + fm * (16 * PADA * 2) + ks * 32);
#pragma unroll
            for (int fn = 0; fn < 4; fn++)
                ldmatrix_x2t(b[fn][0], b[fn][1],
                             stage + bFragBase + fn * 16 + ks * (16 * PADB * 2));
#pragma unroll
            for (int fm = 0; fm < 4; fm++)
#pragma unroll
                for (int fn = 0; fn < 4; fn++)
                    mma_f16_16x8x16(acc[fm][fn][0], acc[fm][fn][1],
                                    acc[fm][fn][2], acc[fm][fn][3],
                                    a[fm][0], a[fm][1], a[fm][2], a[fm][3],
                                    b[fn][0], b[fn][1]);
        }
    }
    CP_WAIT0();

    int toks[4][2];
    if (!GELU) {
#pragma unroll
        for (int fm = 0; fm < 4; fm++) {
            toks[fm][0] = g_ptok[pbase + m0 + mrow + fm * 16 + grp];
            toks[fm][1] = g_ptok[pbase + m0 + mrow + fm * 16 + grp + 8];
        }
    }

#pragma unroll
    for (int fn = 0; fn < 4; fn++) {
        const int col = n0 + nrow + fn * 8 + qid * 2;
        const float2 bv = *reinterpret_cast<const float2*>(bias + (size_t)e * NTOT + col);
#pragma unroll
        for (int fm = 0; fm < 4; fm++) {
#pragma unroll
            for (int h = 0; h < 2; h++) {
                float v0 = acc[fm][fn][h * 2 + 0] + bv.x;
                float v1 = acc[fm][fn][h * 2 + 1] + bv.y;
                if (GELU) {
                    const int prow = pbase + m0 + mrow + fm * 16 + grp + h * 8;
                    v0 = 0.5f * v0 * (1.0f + erff(v0 * 0.7071067811865476f));
                    v1 = 0.5f * v1 * (1.0f + erff(v1 * 0.7071067811865476f));
                    *reinterpret_cast<__half2*>(g_Hh + (size_t)prow * NTOT + col) =
                        __floats2half2_rn(v0, v1);
                } else {
                    const int tok = toks[fm][h];
                    if (tok >= 0) {
                        const float2 xr = *reinterpret_cast<const float2*>(
                            xres + (size_t)tok * NTOT + col);
                        *reinterpret_cast<float2*>(outp + (size_t)tok * NTOT + col) =
                            make_float2(v0 + xr.x, v1 + xr.y);
                    }
                }
            }
        }
    }
#undef LOAD_STAGE
}

// ---------------- losses + state reset for next call ----------------
__global__ void finalize_kernel(float* __restrict__ out, int out_size) {
    if (threadIdx.x == 0) {
        long long base = (long long)T_ * H_;
        if ((long long)out_size >= base + 2) {
            float s = 0.f;
            for (int e = 0; e < E_; e++) {
                float p = g_prob_sum[e] / (float)T_;
                s += p * p;
            }
            out[base] = (float)E_ * s;
            out[base + 1] = g_entropy_sum / (float)T_;
        }
        if ((long long)out_size >= base + 2 + E_) {
            for (int e = 0; e < E_; e++)
                out[base + 2 + e] = (float)g_counts[e];
        }
        for (int e = 0; e < E_; e++) { g_counts[e] = 0; g_prob_sum[e] = 0.f; }
        g_entropy_sum = 0.f;
        g_flag = 0;
    }
}

// ---------------- launch ----------------
extern "C" void kernel_launch(void* const* d_in, const int* in_sizes, int n_in,
                              void* d_out, int out_size) {
    const float* x  = (const float*)d_in[0];
    const float* Wr = (const float*)d_in[1];
    const float* br = (const float*)d_in[2];
    const float* W1 = (const float*)d_in[3];
    const float* b1 = (const float*)d_in[4];
    const float* W2 = (const float*)d_in[5];
    const float* b2 = (const float*)d_in[6];
    float* out = (float*)d_out;

    cudaFuncSetAttribute(moe_gemm<H_, D_, true>,
                         cudaFuncAttributeMaxDynamicSharedMemorySize, GEMM_SMEM);
    cudaFuncSetAttribute(moe_gemm<D_, H_, false>,
                         cudaFuncAttributeMaxDynamicSharedMemorySize, GEMM_SMEM);

    wconv_kernel<0><<<4096, 256>>>(W1);                        // idx 0: W1 first half
    wconv_kernel<1><<<4096, 256>>>(W1);                        // idx 1: W1 second half
    wconv_kernel<2><<<4096, 256>>>(W2);                        // idx 2: W2
    router_kernel<<<T_ / 32, 1024>>>(x, Wr, br);               // idx 3 <- profiled
    scatter_kernel<<<T_ / 256, 256>>>();                       // idx 4
    gather_kernel<<<TPAD_, 128>>>(x);                          // idx 5
    moe_gemm<H_, D_, true ><<<dim3(D_ / 128, T_ / 128, E_), 256, GEMM_SMEM>>>(x, b1, out); // idx 6
    moe_gemm<D_, H_, false><<<dim3(H_ / 128, T_ / 128, E_), 256, GEMM_SMEM>>>(x, b2, out); // idx 7
    finalize_kernel<<<1, 32>>>(out, out_size);                 // idx 8
}

// round 15
// speedup vs baseline: 1.4974x; 1.0275x over previous
#include <cuda_runtime.h>
#include <cuda_fp16.h>
#include <math.h>
#include <stdint.h>

#define B_ 8
#define N_ 2048
#define H_ 1024
#define E_ 8
#define D_ 2048
#define T_ 16384   // B_*N_
#define TPAD_ (T_ + 1024)

// ---------------- scratch (device-side referenced ONLY from device code) ----------------
// Invariant: g_counts/g_prob_sum/g_entropy_sum/g_flag are ZERO on entry to every
// call (BSS for call 1; finalize resets).
__device__ int    g_expert_idx[T_];
__device__ int    g_counts[E_];
__device__ int    g_offsets[E_ + 1];
__device__ int    g_poffsets[E_ + 1];
__device__ int    g_cursor[E_];
__device__ int    g_ptok[TPAD_];
__device__ float  g_prob_sum[E_];
__device__ float  g_entropy_sum;
__device__ volatile int g_flag;
__device__ __half g_Xh[(size_t)TPAD_ * H_];      // gathered tokens, fp16, padded per expert
__device__ __half g_Hh[(size_t)TPAD_ * D_];      // GELU activations, fp16
__device__ __half g_W1h[(size_t)E_ * H_ * D_];   // W1 fp16
__device__ __half g_W2h[(size_t)E_ * D_ * H_];   // W2 fp16

// ---------------- helpers ----------------
__device__ __forceinline__ uint32_t smem_u32(const void* p) {
    uint32_t a;
    asm("{ .reg .u64 t; cvta.to.shared.u64 t, %1; cvt.u32.u64 %0, t; }" : "=r"(a) : "l"(p));
    return a;
}
__device__ __forceinline__ void cp_async16(uint32_t dst, const void* src) {
    asm volatile("cp.async.cg.shared.global [%0], [%1], 16;" :: "r"(dst), "l"(src));
}
#define CP_COMMIT() asm volatile("cp.async.commit_group;" ::: "memory")
#define CP_WAIT1()  asm volatile("cp.async.wait_group 1;" ::: "memory")
#define CP_WAIT0()  asm volatile("cp.async.wait_group 0;" ::: "memory")

__device__ __forceinline__ void ldmatrix_x4(uint32_t& r0, uint32_t& r1,
                                            uint32_t& r2, uint32_t& r3, uint32_t addr) {
    asm volatile("ldmatrix.sync.aligned.m8n8.x4.shared.b16 {%0,%1,%2,%3}, [%4];"
                 : "=r"(r0), "=r"(r1), "=r"(r2), "=r"(r3) : "r"(addr));
}
__device__ __forceinline__ void ldmatrix_x2t(uint32_t& r0, uint32_t& r1, uint32_t addr) {
    asm volatile("ldmatrix.sync.aligned.m8n8.x2.trans.shared.b16 {%0,%1}, [%2];"
                 : "=r"(r0), "=r"(r1) : "r"(addr));
}
__device__ __forceinline__ void mma_f16_16x8x16(float& d0, float& d1, float& d2, float& d3,
                                                uint32_t a0, uint32_t a1, uint32_t a2, uint32_t a3,
                                                uint32_t b0, uint32_t b1) {
    asm volatile(
        "mma.sync.aligned.m16n8k16.row.col.f32.f16.f16.f32 "
        "{%0,%1,%2,%3}, {%4,%5,%6,%7}, {%8,%9}, {%0,%1,%2,%3};"
        : "+f"(d0), "+f"(d1), "+f"(d2), "+f"(d3)
        : "r"(a0), "r"(a1), "r"(a2), "r"(a3), "r"(b0), "r"(b1));
}

// ---------------- W -> fp16 convert (streaming) ----------------
// WHICH 0/1 : halves of W1;  WHICH 2 : all of W2.
template<int WHICH>
__global__ void __launch_bounds__(256) wconv_kernel(const float* __restrict__ W) {
    __half2* d = reinterpret_cast<__half2*>(WHICH == 2 ? g_W2h
                                                       : g_W1h + (WHICH ? (size_t)E_ * H_ * D_ / 2 : 0));
    const float4* s = reinterpret_cast<const float4*>(
        WHICH == 1 ? W + (size_t)E_ * H_ * D_ / 2 : W);
    const int iters = (WHICH == 2) ? 4 : 2;
    const size_t gtid = (size_t)blockIdx.x * 256 + threadIdx.x;
    for (int i = 0; i < iters; i++) {
        size_t idx = gtid + (size_t)i * (4096 * 256);
        float4 v = s[idx];
        d[idx * 2 + 0] = __floats2half2_rn(v.x, v.y);
        d[idx * 2 + 1] = __floats2half2_rn(v.z, v.w);
    }
}

// ---------------- router: conflict-free sWr (stride 10), block-level reduction ----------------
#define WR_PAD 10
__global__ void __launch_bounds__(1024) router_kernel(const float* __restrict__ x,
                                                      const float* __restrict__ Wr,
                                                      const float* __restrict__ br) {
    __shared__ float sWr[H_ * WR_PAD];       // 40 KB; row h at h*10, 8 experts + 2 pad
    __shared__ float s_prob[E_];
    __shared__ float s_ent;
    __shared__ int   s_cnt[E_];
    if (threadIdx.x < E_) { s_prob[threadIdx.x] = 0.f; s_cnt[threadIdx.x] = 0; }
    if (threadIdx.x == 0) s_ent = 0.f;
    for (int i = threadIdx.x; i < H_ * E_; i += blockDim.x) {
        int h = i >> 3, e = i & 7;
        sWr[h * WR_PAD + e] = Wr[i];
    }
    __syncthreads();

    int warp = threadIdx.x >> 5;             // 0..31
    int lane = threadIdx.x & 31;
    int t = blockIdx.x * 32 + warp;

    const float* xr = x + (size_t)t * H_;
    float acc[E_];
#pragma unroll
    for (int e = 0; e < E_; e++) acc[e] = 0.f;
    for (int h = lane; h < H_; h += 32) {
        float xv = xr[h];
        // stride-10 float2 loads: word stride 10 (gcd(10,32)=2, 16-lane cycle) -> conflict-free
        const float2* w = reinterpret_cast<const float2*>(&sWr[h * WR_PAD]);
        float2 w01 = w[0], w23 = w[1], w45 = w[2], w67 = w[3];
        acc[0] += xv * w01.x; acc[1] += xv * w01.y;
        acc[2] += xv * w23.x; acc[3] += xv * w23.y;
        acc[4] += xv * w45.x; acc[5] += xv * w45.y;
        acc[6] += xv * w67.x; acc[7] += xv * w67.y;
    }
#pragma unroll
    for (int e = 0; e < E_; e++) {
#pragma unroll
        for (int o = 16; o > 0; o >>= 1)
            acc[e] += __shfl_xor_sync(0xffffffffu, acc[e], o);
    }
    if (lane == 0) {
        float lg[E_];
        float mx = -1e30f;
        int arg = 0;
#pragma unroll
        for (int e = 0; e < E_; e++) {
            lg[e] = acc[e] + br[e];
            if (lg[e] > mx) { mx = lg[e]; arg = e; }
        }
        float s = 0.f;
#pragma unroll
        for (int e = 0; e < E_; e++) { lg[e] = expf(lg[e] - mx); s += lg[e]; }
        float inv = 1.f / s;
        float ent = 0.f;
#pragma unroll
        for (int e = 0; e < E_; e++) {
            float p = lg[e] * inv;
            atomicAdd(&s_prob[e], p);        // shared atomics: cheap
            ent -= p * logf(p + 1e-8f);
        }
        atomicAdd(&s_ent, ent);
        atomicAdd(&s_cnt[arg], 1);
        g_expert_idx[t] = arg;
    }
    __syncthreads();
    // one global atomic per quantity per block (512 blocks -> 512/address)
    if (threadIdx.x < E_) atomicAdd(&g_prob_sum[threadIdx.x], s_prob[threadIdx.x]);
    else if (threadIdx.x == E_) atomicAdd(&g_entropy_sum, s_ent);
    else if (threadIdx.x >= 16 && threadIdx.x < 16 + E_)
        atomicAdd(&g_counts[threadIdx.x - 16], s_cnt[threadIdx.x - 16]);
}

// ---------------- scatter: scan + warp-aggregated position assignment ----------------
__global__ void __launch_bounds__(256) scatter_kernel() {
    const int t = blockIdx.x * 256 + threadIdx.x;
    if (t == 0) {
        int o = 0, po = 0;
        for (int e = 0; e < E_; e++) {
            g_offsets[e] = o;
            g_cursor[e] = o;
            g_poffsets[e] = po;
            o += g_counts[e];
            po += (g_counts[e] + 127) & ~127;
        }
        g_offsets[E_] = o;
        g_poffsets[E_] = po;
        __threadfence();
        g_flag = 1;
    }
    if (threadIdx.x == 0 && blockIdx.x != 0) {
        while (g_flag == 0) __nanosleep(64);
    }
    __syncthreads();
    __threadfence();

    const int e = g_expert_idx[t];
    unsigned mask = __match_any_sync(0xffffffffu, e);
    int leader = __ffs(mask) - 1;
    int rank = __popc(mask & ((1u << (threadIdx.x & 31)) - 1));
    int base = 0;
    if ((threadIdx.x & 31) == leader)
        base = atomicAdd(&g_cursor[e], __popc(mask));
    base = __shfl_sync(0xffffffffu, base, leader);
    const int pos = base + rank;
    const int p = g_poffsets[e] + (pos - g_offsets[e]);
    g_ptok[p] = t;

    if (blockIdx.x == 0) {
        __syncthreads();
#pragma unroll
        for (int e2 = 0; e2 < E_; e2++) {
            int start = g_poffsets[e2] + g_counts[e2];
            int end = g_poffsets[e2 + 1];
            for (int q = start + threadIdx.x; q < end; q += 256)
                g_ptok[q] = -1;
        }
    }
}

// ---------------- gather: block per padded slot, fp16 convert ----------------
__global__ void __launch_bounds__(128) gather_kernel(const float* __restrict__ x) {
    const int p = blockIdx.x;
    if (p >= g_poffsets[E_]) return;
    const int tok = g_ptok[p];
    __half2* dst = reinterpret_cast<__half2*>(g_Xh + (size_t)p * H_);
    if (tok >= 0) {
        const float4* src = reinterpret_cast<const float4*>(x + (size_t)tok * H_);
        for (int i = threadIdx.x; i < H_ / 4; i += 128) {
            float4 v = src[i];
            dst[i * 2 + 0] = __floats2half2_rn(v.x, v.y);
            dst[i * 2 + 1] = __floats2half2_rn(v.z, v.w);
        }
    } else {
        const __half2 z = __floats2half2_rn(0.f, 0.f);
        for (int i = threadIdx.x; i < H_ / 4; i += 128) {
            dst[i * 2 + 0] = z;
            dst[i * 2 + 1] = z;
        }
    }
}

// ---------------- fp16 mma grouped GEMM: 128x128 tile, 2 CTAs/SM (R9/R10, frozen) ----------------
#define STAGES  3
#define KC      32
#define PADA    40                         // halfs per A row
#define PADB    136                        // halfs per B row (128 + 8)
#define A_HALFS (128 * PADA)               // 5120
#define B_HALFS (KC * PADB)                // 4352
#define STAGE_BYTES ((A_HALFS + B_HALFS) * 2)   // 18944
#define GEMM_SMEM (STAGES * STAGE_BYTES)        // 56832

template<int KTOT, int NTOT, bool GELU>
__global__ void __launch_bounds__(256, 2)
moe_gemm(const float* __restrict__ xres,   // x (residual, GEMM2)
         const float* __restrict__ bias,
         float* __restrict__ outp)
{
    constexpr int CCH = KTOT / KC;
    const __half* A  = GELU ? g_Xh  : g_Hh;
    const __half* Wh = GELU ? g_W1h : g_W2h;

    const int e = blockIdx.z;
    const int pbase = g_poffsets[e];
    const int pcount = g_poffsets[e + 1] - pbase;
    const int m0 = blockIdx.y * 128;
    if (m0 >= pcount) return;
    const int n0 = blockIdx.x * 128;

    extern __shared__ __half smh[];
    const uint32_t smbase = smem_u32(smh);

    const int tid = threadIdx.x;
    const int wid = tid >> 5;
    const int lane = tid & 31;
    const int grp = lane >> 2;
    const int qid = lane & 3;
    const int mrow = (wid & 1) * 64;
    const int nrow = (wid >> 1) * 32;

    const char* aptr[2];
    uint32_t aoff[2];
#pragma unroll
    for (int i = 0; i < 2; i++) {
        int idx = tid + i * 256;
        int row = idx >> 2, c = idx & 3;
        aptr[i] = reinterpret_cast<const char*>(
                      A + (size_t)(pbase + m0 + row) * KTOT) + c * 16;
        aoff[i] = (uint32_t)(row * PADA + c * 8) * 2;
    }
    const char* bptr[2];
    uint32_t boff[2];
#pragma unroll
    for (int i = 0; i < 2; i++) {
        int idx = tid + i * 256;
        int kr = idx >> 4, c = idx & 15;
        bptr[i] = reinterpret_cast<const char*>(
                      Wh + (size_t)e * KTOT * NTOT + (size_t)kr * NTOT + n0) + c * 16;
        boff[i] = (uint32_t)(A_HALFS + kr * PADB + c * 8) * 2;
    }

#define LOAD_STAGE(st, ch) do {                                                     \
        uint32_t _sb = smbase + (uint32_t)(st) * STAGE_BYTES;                       \
        size_t _ga = (size_t)(ch) * (KC * 2);                                       \
        size_t _gb = (size_t)(ch) * ((size_t)KC * NTOT * 2);                        \
        _Pragma("unroll")                                                           \
        for (int _i = 0; _i < 2; _i++) cp_async16(_sb + aoff[_i], aptr[_i] + _ga);  \
        _Pragma("unroll")                                                           \
        for (int _i = 0; _i < 2; _i++) cp_async16(_sb + boff[_i], bptr[_i] + _gb);  \
    } while (0)

    const uint32_t aFragBase =
        ((uint32_t)((mrow + (lane & 15)) * PADA + (lane >> 4) * 8)) * 2;
    const uint32_t bFragBase =
        (uint32_t)(A_HALFS * 2) + ((uint32_t)((lane & 15) * PADB + nrow)) * 2;

    float acc[4][4][4];
#pragma unroll
    for (int i = 0; i < 4; i++)
#pragma unroll
        for (int j = 0; j < 4; j++)
#pragma unroll
            for (int q = 0; q < 4; q++) acc[i][j][q] = 0.f;

    LOAD_STAGE(0, 0); CP_COMMIT();
    LOAD_STAGE(1, 1); CP_COMMIT();

    for (int c = 0; c < CCH; c++) {
        CP_WAIT1();
        __syncthreads();
        if (c + 2 < CCH) LOAD_STAGE((c + 2) % STAGES, c + 2);
        CP_COMMIT();

        const uint32_t stage = smbase + (uint32_t)(c % STAGES) * STAGE_BYTES;

#pragma unroll
        for (int ks = 0; ks < 2; ks++) {
            uint32_t a[4][4], b[4][2];
#pragma unroll
            for (int fm = 0; fm < 4; fm++)
                ldmatrix_x4(a[fm][0], a[fm][1], a[fm][2], a[fm][3],
                            stage + aFragBase + fm * (16 * PADA * 2) + ks * 32);
#pragma unroll
            for (int fn = 0; fn < 4; fn++)
                ldmatrix_x2t(b[fn][0], b[fn][1],
                             stage + bFragBase + fn * 16 + ks * (16 * PADB * 2));
#pragma unroll
            for (int fm = 0; fm < 4; fm++)
#pragma unroll
                for (int fn = 0; fn < 4; fn++)
                    mma_f16_16x8x16(acc[fm][fn][0], acc[fm][fn][1],
                                    acc[fm][fn][2], acc[fm][fn][3],
                                    a[fm][0], a[fm][1], a[fm][2], a[fm][3],
                                    b[fn][0], b[fn][1]);
        }
    }
    CP_WAIT0();

    int toks[4][2];
    if (!GELU) {
#pragma unroll
        for (int fm = 0; fm < 4; fm++) {
            toks[fm][0] = g_ptok[pbase + m0 + mrow + fm * 16 + grp];
            toks[fm][1] = g_ptok[pbase + m0 + mrow + fm * 16 + grp + 8];
        }
    }

#pragma unroll
    for (int fn = 0; fn < 4; fn++) {
        const int col = n0 + nrow + fn * 8 + qid * 2;
        const float2 bv = *reinterpret_cast<const float2*>(bias + (size_t)e * NTOT + col);
#pragma unroll
        for (int fm = 0; fm < 4; fm++) {
#pragma unroll
            for (int h = 0; h < 2; h++) {
                float v0 = acc[fm][fn][h * 2 + 0] + bv.x;
                float v1 = acc[fm][fn][h * 2 + 1] + bv.y;
                if (GELU) {
                    const int prow = pbase + m0 + mrow + fm * 16 + grp + h * 8;
                    v0 = 0.5f * v0 * (1.0f + erff(v0 * 0.7071067811865476f));
                    v1 = 0.5f * v1 * (1.0f + erff(v1 * 0.7071067811865476f));
                    *reinterpret_cast<__half2*>(g_Hh + (size_t)prow * NTOT + col) =
                        __floats2half2_rn(v0, v1);
                } else {
                    const int tok = toks[fm][h];
                    if (tok >= 0) {
                        const float2 xr = *reinterpret_cast<const float2*>(
                            xres + (size_t)tok * NTOT + col);
                        *reinterpret_cast<float2*>(outp + (size_t)tok * NTOT + col) =
                            make_float2(v0 + xr.x, v1 + xr.y);
                    }
                }
            }
        }
    }
#undef LOAD_STAGE
}

// ---------------- losses + state reset for next call ----------------
__global__ void finalize_kernel(float* __restrict__ out, int out_size) {
    if (threadIdx.x == 0) {
        long long base = (long long)T_ * H_;
        if ((long long)out_size >= base + 2) {
            float s = 0.f;
            for (int e = 0; e < E_; e++) {
                float p = g_prob_sum[e] / (float)T_;
                s += p * p;
            }
            out[base] = (float)E_ * s;
            out[base + 1] = g_entropy_sum / (float)T_;
        }
        if ((long long)out_size >= base + 2 + E_) {
            for (int e = 0; e < E_; e++)
                out[base + 2 + e] = (float)g_counts[e];
        }
        for (int e = 0; e < E_; e++) { g_counts[e] = 0; g_prob_sum[e] = 0.f; }
        g_entropy_sum = 0.f;
        g_flag = 0;
    }
}

// ---------------- launch ----------------
extern "C" void kernel_launch(void* const* d_in, const int* in_sizes, int n_in,
                              void* d_out, int out_size) {
    const float* x  = (const float*)d_in[0];
    const float* Wr = (const float*)d_in[1];
    const float* br = (const float*)d_in[2];
    const float* W1 = (const float*)d_in[3];
    const float* b1 = (const float*)d_in[4];
    const float* W2 = (const float*)d_in[5];
    const float* b2 = (const float*)d_in[6];
    float* out = (float*)d_out;

    cudaFuncSetAttribute(moe_gemm<H_, D_, true>,
                         cudaFuncAttributeMaxDynamicSharedMemorySize, GEMM_SMEM);
    cudaFuncSetAttribute(moe_gemm<D_, H_, false>,
                         cudaFuncAttributeMaxDynamicSharedMemorySize, GEMM_SMEM);

    wconv_kernel<0><<<4096, 256>>>(W1);                        // idx 0: W1 first half
    wconv_kernel<1><<<4096, 256>>>(W1);                        // idx 1: W1 second half
    wconv_kernel<2><<<4096, 256>>>(W2);                        // idx 2: W2
    router_kernel<<<T_ / 32, 1024>>>(x, Wr, br);               // idx 3 <- profiled (verify fix)
    scatter_kernel<<<T_ / 256, 256>>>();                       // idx 4
    gather_kernel<<<TPAD_, 128>>>(x);                          // idx 5
    moe_gemm<H_, D_, true ><<<dim3(D_ / 128, T_ / 128, E_), 256, GEMM_SMEM>>>(x, b1, out); // idx 6
    moe_gemm<D_, H_, false><<<dim3(H_ / 128, T_ / 128, E_), 256, GEMM_SMEM>>>(x, b2, out); // idx 7
    finalize_kernel<<<1, 32>>>(out, out_size);                 // idx 8
}

// round 16
// speedup vs baseline: 1.5103x; 1.0086x over previous
#include <cuda_runtime.h>
#include <cuda_fp16.h>
#include <math.h>
#include <stdint.h>

#define B_ 8
#define N_ 2048
#define H_ 1024
#define E_ 8
#define D_ 2048
#define T_ 16384   // B_*N_
#define TPAD_ (T_ + 1024)

// ---------------- scratch (device-side referenced ONLY from device code) ----------------
// Invariant: g_counts/g_prob_sum/g_entropy_sum/g_flag are ZERO on entry to every
// call (BSS for call 1; finalize resets).
__device__ int    g_expert_idx[T_];
__device__ int    g_counts[E_];
__device__ int    g_offsets[E_ + 1];
__device__ int    g_poffsets[E_ + 1];
__device__ int    g_cursor[E_];
__device__ int    g_ptok[TPAD_];
__device__ float  g_prob_sum[E_];
__device__ float  g_entropy_sum;
__device__ volatile int g_flag;
__device__ __half g_Xh[(size_t)TPAD_ * H_];      // gathered tokens, fp16, padded per expert
__device__ __half g_Hh[(size_t)TPAD_ * D_];      // GELU activations, fp16
__device__ __half g_W1h[(size_t)E_ * H_ * D_];   // W1 fp16
__device__ __half g_W2h[(size_t)E_ * D_ * H_];   // W2 fp16

// ---------------- helpers ----------------
__device__ __forceinline__ uint32_t smem_u32(const void* p) {
    uint32_t a;
    asm("{ .reg .u64 t; cvta.to.shared.u64 t, %1; cvt.u32.u64 %0, t; }" : "=r"(a) : "l"(p));
    return a;
}
__device__ __forceinline__ void cp_async16(uint32_t dst, const void* src) {
    asm volatile("cp.async.cg.shared.global [%0], [%1], 16;" :: "r"(dst), "l"(src));
}
#define CP_COMMIT() asm volatile("cp.async.commit_group;" ::: "memory")
#define CP_WAIT1()  asm volatile("cp.async.wait_group 1;" ::: "memory")
#define CP_WAIT0()  asm volatile("cp.async.wait_group 0;" ::: "memory")

__device__ __forceinline__ void ldmatrix_x4(uint32_t& r0, uint32_t& r1,
                                            uint32_t& r2, uint32_t& r3, uint32_t addr) {
    asm volatile("ldmatrix.sync.aligned.m8n8.x4.shared.b16 {%0,%1,%2,%3}, [%4];"
                 : "=r"(r0), "=r"(r1), "=r"(r2), "=r"(r3) : "r"(addr));
}
__device__ __forceinline__ void ldmatrix_x2t(uint32_t& r0, uint32_t& r1, uint32_t addr) {
    asm volatile("ldmatrix.sync.aligned.m8n8.x2.trans.shared.b16 {%0,%1}, [%2];"
                 : "=r"(r0), "=r"(r1) : "r"(addr));
}
__device__ __forceinline__ void mma_f16_16x8x16(float& d0, float& d1, float& d2, float& d3,
                                                uint32_t a0, uint32_t a1, uint32_t a2, uint32_t a3,
                                                uint32_t b0, uint32_t b1) {
    asm volatile(
        "mma.sync.aligned.m16n8k16.row.col.f32.f16.f16.f32 "
        "{%0,%1,%2,%3}, {%4,%5,%6,%7}, {%8,%9}, {%0,%1,%2,%3};"
        : "+f"(d0), "+f"(d1), "+f"(d2), "+f"(d3)
        : "r"(a0), "r"(a1), "r"(a2), "r"(a3), "r"(b0), "r"(b1));
}

// ---------------- fused prep: W1/W2 -> fp16 (blocks 0..2047) + router (blocks 2048..2175) ----------------
// wconv blocks: 1024 blocks per W, 1024 thr x 4 float4 = 4096 float4/block.
// router blocks: 128 blocks, 32 warps x 4 tokens = 128 tokens/block.
#define WR_PAD 10
#define NCONV 2048
#define NROUTE 128

__global__ void __launch_bounds__(1024) fused_prep(const float* __restrict__ x,
                                                   const float* __restrict__ Wr,
                                                   const float* __restrict__ br,
                                                   const float* __restrict__ W1,
                                                   const float* __restrict__ W2) {
    if (blockIdx.x < NCONV) {
        // ---- streaming W convert (DRAM-bound) ----
        int bi = blockIdx.x;
        const float4* s;
        __half2* d;
        if (bi < NCONV / 2) {
            s = reinterpret_cast<const float4*>(W1);
            d = reinterpret_cast<__half2*>(g_W1h);
        } else {
            s = reinterpret_cast<const float4*>(W2);
            d = reinterpret_cast<__half2*>(g_W2h);
            bi -= NCONV / 2;
        }
        size_t base = (size_t)bi * 4096 + threadIdx.x;
#pragma unroll
        for (int i = 0; i < 4; i++) {
            size_t idx = base + (size_t)i * 1024;
            float4 v = s[idx];
            d[idx * 2 + 0] = __floats2half2_rn(v.x, v.y);
            d[idx * 2 + 1] = __floats2half2_rn(v.z, v.w);
        }
        return;
    }

    // ---- router: 4 tokens per warp (W crossbar bytes /4) ----
    __shared__ float sWr[H_ * WR_PAD];       // 40 KB
    __shared__ float s_prob[E_];
    __shared__ float s_ent;
    __shared__ int   s_cnt[E_];
    if (threadIdx.x < E_) { s_prob[threadIdx.x] = 0.f; s_cnt[threadIdx.x] = 0; }
    if (threadIdx.x == 0) s_ent = 0.f;
    for (int i = threadIdx.x; i < H_ * E_; i += blockDim.x) {
        int h = i >> 3, e = i & 7;
        sWr[h * WR_PAD + e] = Wr[i];
    }
    __syncthreads();

    const int rb = blockIdx.x - NCONV;       // 0..127
    const int warp = threadIdx.x >> 5;       // 0..31
    const int lane = threadIdx.x & 31;
    const int t0 = (rb * 32 + warp) * 4;

    const float* xr = x + (size_t)t0 * H_;
    float acc[4][E_];
#pragma unroll
    for (int j = 0; j < 4; j++)
#pragma unroll
        for (int e = 0; e < E_; e++) acc[j][e] = 0.f;

    for (int h = lane; h < H_; h += 32) {
        const float2* w = reinterpret_cast<const float2*>(&sWr[h * WR_PAD]);
        float2 w01 = w[0], w23 = w[1], w45 = w[2], w67 = w[3];
        float xv0 = xr[h];
        float xv1 = xr[H_ + h];
        float xv2 = xr[2 * H_ + h];
        float xv3 = xr[3 * H_ + h];
#define ROUT_ACC(j, xv) \
        acc[j][0] += (xv) * w01.x; acc[j][1] += (xv) * w01.y; \
        acc[j][2] += (xv) * w23.x; acc[j][3] += (xv) * w23.y; \
        acc[j][4] += (xv) * w45.x; acc[j][5] += (xv) * w45.y; \
        acc[j][6] += (xv) * w67.x; acc[j][7] += (xv) * w67.y;
        ROUT_ACC(0, xv0) ROUT_ACC(1, xv1) ROUT_ACC(2, xv2) ROUT_ACC(3, xv3)
#undef ROUT_ACC
    }
#pragma unroll
    for (int j = 0; j < 4; j++)
#pragma unroll
        for (int e = 0; e < E_; e++) {
#pragma unroll
            for (int o = 16; o > 0; o >>= 1)
                acc[j][e] += __shfl_xor_sync(0xffffffffu, acc[j][e], o);
        }

    if (lane < 4) {                          // lane j handles token t0+j
        const int j = lane;
        float lg[E_];
        float mx = -1e30f;
        int arg = 0;
#pragma unroll
        for (int e = 0; e < E_; e++) {
            lg[e] = acc[j][e] + br[e];
            if (lg[e] > mx) { mx = lg[e]; arg = e; }
        }
        float s = 0.f;
#pragma unroll
        for (int e = 0; e < E_; e++) { lg[e] = expf(lg[e] - mx); s += lg[e]; }
        float inv = 1.f / s;
        float ent = 0.f;
#pragma unroll
        for (int e = 0; e < E_; e++) {
            float p = lg[e] * inv;
            atomicAdd(&s_prob[e], p);
            ent -= p * logf(p + 1e-8f);
        }
        atomicAdd(&s_ent, ent);
        atomicAdd(&s_cnt[arg], 1);
        g_expert_idx[t0 + j] = arg;
    }
    __syncthreads();
    if (threadIdx.x < E_) atomicAdd(&g_prob_sum[threadIdx.x], s_prob[threadIdx.x]);
    else if (threadIdx.x == E_) atomicAdd(&g_entropy_sum, s_ent);
    else if (threadIdx.x >= 16 && threadIdx.x < 16 + E_)
        atomicAdd(&g_counts[threadIdx.x - 16], s_cnt[threadIdx.x - 16]);
}

// ---------------- scatter: scan + warp-aggregated position assignment ----------------
__global__ void __launch_bounds__(256) scatter_kernel() {
    const int t = blockIdx.x * 256 + threadIdx.x;
    if (t == 0) {
        int o = 0, po = 0;
        for (int e = 0; e < E_; e++) {
            g_offsets[e] = o;
            g_cursor[e] = o;
            g_poffsets[e] = po;
            o += g_counts[e];
            po += (g_counts[e] + 127) & ~127;
        }
        g_offsets[E_] = o;
        g_poffsets[E_] = po;
        __threadfence();
        g_flag = 1;
    }
    if (threadIdx.x == 0 && blockIdx.x != 0) {
        while (g_flag == 0) __nanosleep(64);
    }
    __syncthreads();
    __threadfence();

    const int e = g_expert_idx[t];
    unsigned mask = __match_any_sync(0xffffffffu, e);
    int leader = __ffs(mask) - 1;
    int rank = __popc(mask & ((1u << (threadIdx.x & 31)) - 1));
    int base = 0;
    if ((threadIdx.x & 31) == leader)
        base = atomicAdd(&g_cursor[e], __popc(mask));
    base = __shfl_sync(0xffffffffu, base, leader);
    const int pos = base + rank;
    const int p = g_poffsets[e] + (pos - g_offsets[e]);
    g_ptok[p] = t;
}

// ---------------- gather: block per padded slot; handles pads itself ----------------
__global__ void __launch_bounds__(128) gather_kernel(const float* __restrict__ x) {
    const int p = blockIdx.x;
    if (p >= g_poffsets[E_]) return;
    int e = 0;
#pragma unroll
    for (int i = 1; i < E_; i++)
        if (p >= g_poffsets[i]) e = i;
    const bool pad = (p - g_poffsets[e]) >= g_counts[e];

    __half2* dst = reinterpret_cast<__half2*>(g_Xh + (size_t)p * H_);
    if (!pad) {
        const int tok = g_ptok[p];
        const float4* src = reinterpret_cast<const float4*>(x + (size_t)tok * H_);
        for (int i = threadIdx.x; i < H_ / 4; i += 128) {
            float4 v = src[i];
            dst[i * 2 + 0] = __floats2half2_rn(v.x, v.y);
            dst[i * 2 + 1] = __floats2half2_rn(v.z, v.w);
        }
    } else {
        if (threadIdx.x == 0) g_ptok[p] = -1;   // GEMM2 epilogue relies on this
        const __half2 z = __floats2half2_rn(0.f, 0.f);
        for (int i = threadIdx.x; i < H_ / 4; i += 128) {
            dst[i * 2 + 0] = z;
            dst[i * 2 + 1] = z;
        }
    }
}

// ---------------- fp16 mma grouped GEMM: 128x128 tile, 2 CTAs/SM (R9/R10, frozen) ----------------
#define STAGES  3
#define KC      32
#define PADA    40                         // halfs per A row
#define PADB    136                        // halfs per B row (128 + 8)
#define A_HALFS (128 * PADA)               // 5120
#define B_HALFS (KC * PADB)                // 4352
#define STAGE_BYTES ((A_HALFS + B_HALFS) * 2)   // 18944
#define GEMM_SMEM (STAGES * STAGE_BYTES)        // 56832

template<int KTOT, int NTOT, bool GELU>
__global__ void __launch_bounds__(256, 2)
moe_gemm(const float* __restrict__ xres,   // x (residual, GEMM2)
         const float* __restrict__ bias,
         float* __restrict__ outp)
{
    constexpr int CCH = KTOT / KC;
    const __half* A  = GELU ? g_Xh  : g_Hh;
    const __half* Wh = GELU ? g_W1h : g_W2h;

    const int e = blockIdx.z;
    const int pbase = g_poffsets[e];
    const int pcount = g_poffsets[e + 1] - pbase;
    const int m0 = blockIdx.y * 128;
    if (m0 >= pcount) return;
    const int n0 = blockIdx.x * 128;

    extern __shared__ __half smh[];
    const uint32_t smbase = smem_u32(smh);

    const int tid = threadIdx.x;
    const int wid = tid >> 5;
    const int lane = tid & 31;
    const int grp = lane >> 2;
    const int qid = lane & 3;
    const int mrow = (wid & 1) * 64;
    const int nrow = (wid >> 1) * 32;

    const char* aptr[2];
    uint32_t aoff[2];
#pragma unroll
    for (int i = 0; i < 2; i++) {
        int idx = tid + i * 256;
        int row = idx >> 2, c = idx & 3;
        aptr[i] = reinterpret_cast<const char*>(
                      A + (size_t)(pbase + m0 + row) * KTOT) + c * 16;
        aoff[i] = (uint32_t)(row * PADA + c * 8) * 2;
    }
    const char* bptr[2];
    uint32_t boff[2];
#pragma unroll
    for (int i = 0; i < 2; i++) {
        int idx = tid + i * 256;
        int kr = idx >> 4, c = idx & 15;
        bptr[i] = reinterpret_cast<const char*>(
                      Wh + (size_t)e * KTOT * NTOT + (size_t)kr * NTOT + n0) + c * 16;
        boff[i] = (uint32_t)(A_HALFS + kr * PADB + c * 8) * 2;
    }

#define LOAD_STAGE(st, ch) do {                                                     \
        uint32_t _sb = smbase + (uint32_t)(st) * STAGE_BYTES;                       \
        size_t _ga = (size_t)(ch) * (KC * 2);                                       \
        size_t _gb = (size_t)(ch) * ((size_t)KC * NTOT * 2);                        \
        _Pragma("unroll")                                                           \
        for (int _i = 0; _i < 2; _i++) cp_async16(_sb + aoff[_i], aptr[_i] + _ga);  \
        _Pragma("unroll")                                                           \
        for (int _i = 0; _i < 2; _i++) cp_async16(_sb + boff[_i], bptr[_i] + _gb);  \
    } while (0)

    const uint32_t aFragBase =
        ((uint32_t)((mrow + (lane & 15)) * PADA + (lane >> 4) * 8)) * 2;
    const uint32_t bFragBase =
        (uint32_t)(A_HALFS * 2) + ((uint32_t)((lane & 15) * PADB + nrow)) * 2;

    float acc[4][4][4];
#pragma unroll
    for (int i = 0; i < 4; i++)
#pragma unroll
        for (int j = 0; j < 4; j++)
#pragma unroll
            for (int q = 0; q < 4; q++) acc[i][j][q] = 0.f;

    LOAD_STAGE(0, 0); CP_COMMIT();
    LOAD_STAGE(1, 1); CP_COMMIT();

    for (int c = 0; c < CCH; c++) {
        CP_WAIT1();
        __syncthreads();
        if (c + 2 < CCH) LOAD_STAGE((c + 2) % STAGES, c + 2);
        CP_COMMIT();

        const uint32_t stage = smbase + (uint32_t)(c % STAGES) * STAGE_BYTES;

#pragma unroll
        for (int ks = 0; ks < 2; ks++) {
            uint32_t a[4][4], b[4][2];
#pragma unroll
            for (int fm = 0; fm < 4; fm++)
                ldmatrix_x4(a[fm][0], a[fm][1], a[fm][2], a[fm][3],
                            stage + aFragBase + fm * (16 * PADA * 2) + ks * 32);
#pragma unroll
            for (int fn = 0; fn < 4; fn++)
                ldmatrix_x2t(b[fn][0], b[fn][1],
                             stage + bFragBase + fn * 16 + ks * (16 * PADB * 2));
#pragma unroll
            for (int fm = 0; fm < 4; fm++)
#pragma unroll
                for (int fn = 0; fn < 4; fn++)
                    mma_f16_16x8x16(acc[fm][fn][0], acc[fm][fn][1],
                                    acc[fm][fn][2], acc[fm][fn][3],
                                    a[fm][0], a[fm][1], a[fm][2], a[fm][3],
                                    b[fn][0], b[fn][1]);
        }
    }
    CP_WAIT0();

    int toks[4][2];
    if (!GELU) {
#pragma unroll
        for (int fm = 0; fm < 4; fm++) {
            toks[fm][0] = g_ptok[pbase + m0 + mrow + fm * 16 + grp];
            toks[fm][1] = g_ptok[pbase + m0 + mrow + fm * 16 + grp + 8];
        }
    }

#pragma unroll
    for (int fn = 0; fn < 4; fn++) {
        const int col = n0 + nrow + fn * 8 + qid * 2;
        const float2 bv = *reinterpret_cast<const float2*>(bias + (size_t)e * NTOT + col);
#pragma unroll
        for (int fm = 0; fm < 4; fm++) {
#pragma unroll
            for (int h = 0; h < 2; h++) {
                float v0 = acc[fm][fn][h * 2 + 0] + bv.x;
                float v1 = acc[fm][fn][h * 2 + 1] + bv.y;
                if (GELU) {
                    const int prow = pbase + m0 + mrow + fm * 16 + grp + h * 8;
                    v0 = 0.5f * v0 * (1.0f + erff(v0 * 0.7071067811865476f));
                    v1 = 0.5f * v1 * (1.0f + erff(v1 * 0.7071067811865476f));
                    *reinterpret_cast<__half2*>(g_Hh + (size_t)prow * NTOT + col) =
                        __floats2half2_rn(v0, v1);
                } else {
                    const int tok = toks[fm][h];
                    if (tok >= 0) {
                        const float2 xr = *reinterpret_cast<const float2*>(
                            xres + (size_t)tok * NTOT + col);
                        *reinterpret_cast<float2*>(outp + (size_t)tok * NTOT + col) =
                            make_float2(v0 + xr.x, v1 + xr.y);
                    }
                }
            }
        }
    }
#undef LOAD_STAGE
}

// ---------------- losses + state reset for next call ----------------
__global__ void finalize_kernel(float* __restrict__ out, int out_size) {
    if (threadIdx.x == 0) {
        long long base = (long long)T_ * H_;
        if ((long long)out_size >= base + 2) {
            float s = 0.f;
            for (int e = 0; e < E_; e++) {
                float p = g_prob_sum[e] / (float)T_;
                s += p * p;
            }
            out[base] = (float)E_ * s;
            out[base + 1] = g_entropy_sum / (float)T_;
        }
        if ((long long)out_size >= base + 2 + E_) {
            for (int e = 0; e < E_; e++)
                out[base + 2 + e] = (float)g_counts[e];
        }
        for (int e = 0; e < E_; e++) { g_counts[e] = 0; g_prob_sum[e] = 0.f; }
        g_entropy_sum = 0.f;
        g_flag = 0;
    }
}

// ---------------- launch ----------------
extern "C" void kernel_launch(void* const* d_in, const int* in_sizes, int n_in,
                              void* d_out, int out_size) {
    const float* x  = (const float*)d_in[0];
    const float* Wr = (const float*)d_in[1];
    const float* br = (const float*)d_in[2];
    const float* W1 = (const float*)d_in[3];
    const float* b1 = (const float*)d_in[4];
    const float* W2 = (const float*)d_in[5];
    const float* b2 = (const float*)d_in[6];
    float* out = (float*)d_out;

    cudaFuncSetAttribute(moe_gemm<H_, D_, true>,
                         cudaFuncAttributeMaxDynamicSharedMemorySize, GEMM_SMEM);
    cudaFuncSetAttribute(moe_gemm<D_, H_, false>,
                         cudaFuncAttributeMaxDynamicSharedMemorySize, GEMM_SMEM);

    fused_prep<<<NCONV + NROUTE, 1024>>>(x, Wr, br, W1, W2);   // idx 0: wconv + router overlapped
    scatter_kernel<<<T_ / 256, 256>>>();                       // idx 1
    gather_kernel<<<TPAD_, 128>>>(x);                          // idx 2
    moe_gemm<H_, D_, true ><<<dim3(D_ / 128, T_ / 128, E_), 256, GEMM_SMEM>>>(x, b1, out); // idx 3
    moe_gemm<D_, H_, false><<<dim3(H_ / 128, T_ / 128, E_), 256, GEMM_SMEM>>>(x, b2, out); // idx 4
    finalize_kernel<<<1, 32>>>(out, out_size);                 // idx 5
}

// round 17
// speedup vs baseline: 1.5133x; 1.0019x over previous
#include <cuda_runtime.h>
#include <cuda_fp16.h>
#include <math.h>
#include <stdint.h>

#define B_ 8
#define N_ 2048
#define H_ 1024
#define E_ 8
#define D_ 2048
#define T_ 16384   // B_*N_
#define TPAD_ (T_ + 1024)

// ---------------- scratch (device-side referenced ONLY from device code) ----------------
// Invariant: g_counts/g_prob_sum/g_entropy_sum/g_flag/g_rdone are ZERO on entry to
// every call (BSS for call 1; finalize resets).
__device__ int    g_expert_idx[T_];
__device__ int    g_counts[E_];
__device__ int    g_offsets[E_ + 1];
__device__ int    g_poffsets[E_ + 1];
__device__ int    g_cursor[E_];
__device__ int    g_ptok[TPAD_];
__device__ float  g_prob_sum[E_];
__device__ float  g_entropy_sum;
__device__ volatile int g_flag;
__device__ int    g_rdone;
__device__ __half g_Xh[(size_t)TPAD_ * H_];      // gathered tokens, fp16, padded per expert
__device__ __half g_Hh[(size_t)TPAD_ * D_];      // GELU activations, fp16
__device__ __half g_W1h[(size_t)E_ * H_ * D_];   // W1 fp16
__device__ __half g_W2h[(size_t)E_ * D_ * H_];   // W2 fp16

// ---------------- helpers ----------------
__device__ __forceinline__ uint32_t smem_u32(const void* p) {
    uint32_t a;
    asm("{ .reg .u64 t; cvta.to.shared.u64 t, %1; cvt.u32.u64 %0, t; }" : "=r"(a) : "l"(p));
    return a;
}
__device__ __forceinline__ void cp_async16(uint32_t dst, const void* src) {
    asm volatile("cp.async.cg.shared.global [%0], [%1], 16;" :: "r"(dst), "l"(src));
}
#define CP_COMMIT() asm volatile("cp.async.commit_group;" ::: "memory")
#define CP_WAIT1()  asm volatile("cp.async.wait_group 1;" ::: "memory")
#define CP_WAIT0()  asm volatile("cp.async.wait_group 0;" ::: "memory")

__device__ __forceinline__ void ldmatrix_x4(uint32_t& r0, uint32_t& r1,
                                            uint32_t& r2, uint32_t& r3, uint32_t addr) {
    asm volatile("ldmatrix.sync.aligned.m8n8.x4.shared.b16 {%0,%1,%2,%3}, [%4];"
                 : "=r"(r0), "=r"(r1), "=r"(r2), "=r"(r3) : "r"(addr));
}
__device__ __forceinline__ void ldmatrix_x2t(uint32_t& r0, uint32_t& r1, uint32_t addr) {
    asm volatile("ldmatrix.sync.aligned.m8n8.x2.trans.shared.b16 {%0,%1}, [%2];"
                 : "=r"(r0), "=r"(r1) : "r"(addr));
}
__device__ __forceinline__ void mma_f16_16x8x16(float& d0, float& d1, float& d2, float& d3,
                                                uint32_t a0, uint32_t a1, uint32_t a2, uint32_t a3,
                                                uint32_t b0, uint32_t b1) {
    asm volatile(
        "mma.sync.aligned.m16n8k16.row.col.f32.f16.f16.f32 "
        "{%0,%1,%2,%3}, {%4,%5,%6,%7}, {%8,%9}, {%0,%1,%2,%3};"
        : "+f"(d0), "+f"(d1), "+f"(d2), "+f"(d3)
        : "r"(a0), "r"(a1), "r"(a2), "r"(a3), "r"(b0), "r"(b1));
}

// ---------------- fused prep: router (0..127) + scatter (128..143) + wconv (144..2191) ----
// Critical-path roles at LOW block indices so wave 1 starts them immediately;
// DRAM-bound conv fills the remaining slots and overlaps the router->scatter chain.
#define WR_PAD 10
#define NROUTE 128
#define NSCAT  16
#define NCONV  2048

__global__ void __launch_bounds__(1024) fused_prep(const float* __restrict__ x,
                                                   const float* __restrict__ Wr,
                                                   const float* __restrict__ br,
                                                   const float* __restrict__ W1,
                                                   const float* __restrict__ W2) {
    // ================= conv role =================
    if (blockIdx.x >= NROUTE + NSCAT) {
        int bi = blockIdx.x - (NROUTE + NSCAT);
        const float4* s;
        __half2* d;
        if (bi < NCONV / 2) {
            s = reinterpret_cast<const float4*>(W1);
            d = reinterpret_cast<__half2*>(g_W1h);
        } else {
            s = reinterpret_cast<const float4*>(W2);
            d = reinterpret_cast<__half2*>(g_W2h);
            bi -= NCONV / 2;
        }
        size_t base = (size_t)bi * 4096 + threadIdx.x;
#pragma unroll
        for (int i = 0; i < 4; i++) {
            size_t idx = base + (size_t)i * 1024;
            float4 v = s[idx];
            d[idx * 2 + 0] = __floats2half2_rn(v.x, v.y);
            d[idx * 2 + 1] = __floats2half2_rn(v.z, v.w);
        }
        return;
    }

    // ================= scatter role =================
    if (blockIdx.x >= NROUTE) {
        const int sb = blockIdx.x - NROUTE;          // 0..15
        // wait for all router blocks
        if (threadIdx.x == 0) {
            while (*(volatile int*)&g_rdone != NROUTE) __nanosleep(64);
        }
        __syncthreads();
        __threadfence();
        // block sb==0, thread 0: exclusive scan, then release the flag
        if (sb == 0 && threadIdx.x == 0) {
            int o = 0, po = 0;
            for (int e = 0; e < E_; e++) {
                g_offsets[e] = o;
                g_cursor[e] = o;
                g_poffsets[e] = po;
                o += g_counts[e];
                po += (g_counts[e] + 127) & ~127;
            }
            g_offsets[E_] = o;
            g_poffsets[E_] = po;
            __threadfence();
            g_flag = 1;
        }
        if (threadIdx.x == 0 && sb != 0) {
            while (g_flag == 0) __nanosleep(64);
        }
        __syncthreads();
        __threadfence();

        const int t = sb * 1024 + threadIdx.x;
        const int e = g_expert_idx[t];
        unsigned mask = __match_any_sync(0xffffffffu, e);
        int leader = __ffs(mask) - 1;
        int rank = __popc(mask & ((1u << (threadIdx.x & 31)) - 1));
        int base = 0;
        if ((threadIdx.x & 31) == leader)
            base = atomicAdd(&g_cursor[e], __popc(mask));
        base = __shfl_sync(0xffffffffu, base, leader);
        const int pos = base + rank;
        const int p = g_poffsets[e] + (pos - g_offsets[e]);
        g_ptok[p] = t;
        return;
    }

    // ================= router role (blocks 0..127) =================
    __shared__ float sWr[H_ * WR_PAD];       // 40 KB
    __shared__ float s_prob[E_];
    __shared__ float s_ent;
    __shared__ int   s_cnt[E_];
    if (threadIdx.x < E_) { s_prob[threadIdx.x] = 0.f; s_cnt[threadIdx.x] = 0; }
    if (threadIdx.x == 0) s_ent = 0.f;
    for (int i = threadIdx.x; i < H_ * E_; i += blockDim.x) {
        int h = i >> 3, e = i & 7;
        sWr[h * WR_PAD + e] = Wr[i];
    }
    __syncthreads();

    const int rb = blockIdx.x;               // 0..127
    const int warp = threadIdx.x >> 5;       // 0..31
    const int lane = threadIdx.x & 31;
    const int t0 = (rb * 32 + warp) * 4;

    const float* xr = x + (size_t)t0 * H_;
    float acc[4][E_];
#pragma unroll
    for (int j = 0; j < 4; j++)
#pragma unroll
        for (int e = 0; e < E_; e++) acc[j][e] = 0.f;

    for (int h = lane; h < H_; h += 32) {
        const float2* w = reinterpret_cast<const float2*>(&sWr[h * WR_PAD]);
        float2 w01 = w[0], w23 = w[1], w45 = w[2], w67 = w[3];
        float xv0 = xr[h];
        float xv1 = xr[H_ + h];
        float xv2 = xr[2 * H_ + h];
        float xv3 = xr[3 * H_ + h];
#define ROUT_ACC(j, xv) \
        acc[j][0] += (xv) * w01.x; acc[j][1] += (xv) * w01.y; \
        acc[j][2] += (xv) * w23.x; acc[j][3] += (xv) * w23.y; \
        acc[j][4] += (xv) * w45.x; acc[j][5] += (xv) * w45.y; \
        acc[j][6] += (xv) * w67.x; acc[j][7] += (xv) * w67.y;
        ROUT_ACC(0, xv0) ROUT_ACC(1, xv1) ROUT_ACC(2, xv2) ROUT_ACC(3, xv3)
#undef ROUT_ACC
    }
#pragma unroll
    for (int j = 0; j < 4; j++)
#pragma unroll
        for (int e = 0; e < E_; e++) {
#pragma unroll
            for (int o = 16; o > 0; o >>= 1)
                acc[j][e] += __shfl_xor_sync(0xffffffffu, acc[j][e], o);
        }

    if (lane < 4) {                          // lane j handles token t0+j
        const int j = lane;
        float lg[E_];
        float mx = -1e30f;
        int arg = 0;
#pragma unroll
        for (int e = 0; e < E_; e++) {
            lg[e] = acc[j][e] + br[e];
            if (lg[e] > mx) { mx = lg[e]; arg = e; }
        }
        float s = 0.f;
#pragma unroll
        for (int e = 0; e < E_; e++) { lg[e] = expf(lg[e] - mx); s += lg[e]; }
        float inv = 1.f / s;
        float ent = 0.f;
#pragma unroll
        for (int e = 0; e < E_; e++) {
            float p = lg[e] * inv;
            atomicAdd(&s_prob[e], p);
            ent -= p * logf(p + 1e-8f);
        }
        atomicAdd(&s_ent, ent);
        atomicAdd(&s_cnt[arg], 1);
        g_expert_idx[t0 + j] = arg;
    }
    __syncthreads();
    if (threadIdx.x < E_) atomicAdd(&g_prob_sum[threadIdx.x], s_prob[threadIdx.x]);
    else if (threadIdx.x == E_) atomicAdd(&g_entropy_sum, s_ent);
    else if (threadIdx.x >= 16 && threadIdx.x < 16 + E_)
        atomicAdd(&g_counts[threadIdx.x - 16], s_cnt[threadIdx.x - 16]);
    __syncthreads();
    if (threadIdx.x == 0) {
        __threadfence();
        atomicAdd(&g_rdone, 1);              // signal scatter blocks
    }
}

// ---------------- gather: block per padded slot; handles pads itself ----------------
__global__ void __launch_bounds__(128) gather_kernel(const float* __restrict__ x) {
    const int p = blockIdx.x;
    if (p >= g_poffsets[E_]) return;
    int e = 0;
#pragma unroll
    for (int i = 1; i < E_; i++)
        if (p >= g_poffsets[i]) e = i;
    const bool pad = (p - g_poffsets[e]) >= g_counts[e];

    __half2* dst = reinterpret_cast<__half2*>(g_Xh + (size_t)p * H_);
    if (!pad) {
        const int tok = g_ptok[p];
        const float4* src = reinterpret_cast<const float4*>(x + (size_t)tok * H_);
        for (int i = threadIdx.x; i < H_ / 4; i += 128) {
            float4 v = src[i];
            dst[i * 2 + 0] = __floats2half2_rn(v.x, v.y);
            dst[i * 2 + 1] = __floats2half2_rn(v.z, v.w);
        }
    } else {
        if (threadIdx.x == 0) g_ptok[p] = -1;   // GEMM2 epilogue relies on this
        const __half2 z = __floats2half2_rn(0.f, 0.f);
        for (int i = threadIdx.x; i < H_ / 4; i += 128) {
            dst[i * 2 + 0] = z;
            dst[i * 2 + 1] = z;
        }
    }
}

// ---------------- fp16 mma grouped GEMM: 128x128 tile, 2 CTAs/SM (R9/R10, frozen) ----------------
#define STAGES  3
#define KC      32
#define PADA    40                         // halfs per A row
#define PADB    136                        // halfs per B row (128 + 8)
#define A_HALFS (128 * PADA)               // 5120
#define B_HALFS (KC * PADB)                // 4352
#define STAGE_BYTES ((A_HALFS + B_HALFS) * 2)   // 18944
#define GEMM_SMEM (STAGES * STAGE_BYTES)        // 56832

template<int KTOT, int NTOT, bool GELU>
__global__ void __launch_bounds__(256, 2)
moe_gemm(const float* __restrict__ xres,   // x (residual, GEMM2)
         const float* __restrict__ bias,
         float* __restrict__ outp)
{
    constexpr int CCH = KTOT / KC;
    const __half* A  = GELU ? g_Xh  : g_Hh;
    const __half* Wh = GELU ? g_W1h : g_W2h;

    const int e = blockIdx.z;
    const int pbase = g_poffsets[e];
    const int pcount = g_poffsets[e + 1] - pbase;
    const int m0 = blockIdx.y * 128;
    if (m0 >= pcount) return;
    const int n0 = blockIdx.x * 128;

    extern __shared__ __half smh[];
    const uint32_t smbase = smem_u32(smh);

    const int tid = threadIdx.x;
    const int wid = tid >> 5;
    const int lane = tid & 31;
    const int grp = lane >> 2;
    const int qid = lane & 3;
    const int mrow = (wid & 1) * 64;
    const int nrow = (wid >> 1) * 32;

    const char* aptr[2];
    uint32_t aoff[2];
#pragma unroll
    for (int i = 0; i < 2; i++) {
        int idx = tid + i * 256;
        int row = idx >> 2, c = idx & 3;
        aptr[i] = reinterpret_cast<const char*>(
                      A + (size_t)(pbase + m0 + row) * KTOT) + c * 16;
        aoff[i] = (uint32_t)(row * PADA + c * 8) * 2;
    }
    const char* bptr[2];
    uint32_t boff[2];
#pragma unroll
    for (int i = 0; i < 2; i++) {
        int idx = tid + i * 256;
        int kr = idx >> 4, c = idx & 15;
        bptr[i] = reinterpret_cast<const char*>(
                      Wh + (size_t)e * KTOT * NTOT + (size_t)kr * NTOT + n0) + c * 16;
        boff[i] = (uint32_t)(A_HALFS + kr * PADB + c * 8) * 2;
    }

#define LOAD_STAGE(st, ch) do {                                                     \
        uint32_t _sb = smbase + (uint32_t)(st) * STAGE_BYTES;                       \
        size_t _ga = (size_t)(ch) * (KC * 2);                                       \
        size_t _gb = (size_t)(ch) * ((size_t)KC * NTOT * 2);                        \
        _Pragma("unroll")                                                           \
        for (int _i = 0; _i < 2; _i++) cp_async16(_sb + aoff[_i], aptr[_i] + _ga);  \
        _Pragma("unroll")                                                           \
        for (int _i = 0; _i < 2; _i++) cp_async16(_sb + boff[_i], bptr[_i] + _gb);  \
    } while (0)

    const uint32_t aFragBase =
        ((uint32_t)((mrow + (lane & 15)) * PADA + (lane >> 4) * 8)) * 2;
    const uint32_t bFragBase =
        (uint32_t)(A_HALFS * 2) + ((uint32_t)((lane & 15) * PADB + nrow)) * 2;

    float acc[4][4][4];
#pragma unroll
    for (int i = 0; i < 4; i++)
#pragma unroll
        for (int j = 0; j < 4; j++)
#pragma unroll
            for (int q = 0; q < 4; q++) acc[i][j][q] = 0.f;

    LOAD_STAGE(0, 0); CP_COMMIT();
    LOAD_STAGE(1, 1); CP_COMMIT();

    for (int c = 0; c < CCH; c++) {
        CP_WAIT1();
        __syncthreads();
        if (c + 2 < CCH) LOAD_STAGE((c + 2) % STAGES, c + 2);
        CP_COMMIT();

        const uint32_t stage = smbase + (uint32_t)(c % STAGES) * STAGE_BYTES;

#pragma unroll
        for (int ks = 0; ks < 2; ks++) {
            uint32_t a[4][4], b[4][2];
#pragma unroll
            for (int fm = 0; fm < 4; fm++)
                ldmatrix_x4(a[fm][0], a[fm][1], a[fm][2], a[fm][3],
                            stage + aFragBase + fm * (16 * PADA * 2) + ks * 32);
#pragma unroll
            for (int fn = 0; fn < 4; fn++)
                ldmatrix_x2t(b[fn][0], b[fn][1],
                             stage + bFragBase + fn * 16 + ks * (16 * PADB * 2));
#pragma unroll
            for (int fm = 0; fm < 4; fm++)
#pragma unroll
                for (int fn = 0; fn < 4; fn++)
                    mma_f16_16x8x16(acc[fm][fn][0], acc[fm][fn][1],
                                    acc[fm][fn][2], acc[fm][fn][3],
                                    a[fm][0], a[fm][1], a[fm][2], a[fm][3],
                                    b[fn][0], b[fn][1]);
        }
    }
    CP_WAIT0();

    int toks[4][2];
    if (!GELU) {
#pragma unroll
        for (int fm = 0; fm < 4; fm++) {
            toks[fm][0] = g_ptok[pbase + m0 + mrow + fm * 16 + grp];
            toks[fm][1] = g_ptok[pbase + m0 + mrow + fm * 16 + grp + 8];
        }
    }

#pragma unroll
    for (int fn = 0; fn < 4; fn++) {
        const int col = n0 + nrow + fn * 8 + qid * 2;
        const float2 bv = *reinterpret_cast<const float2*>(bias + (size_t)e * NTOT + col);
#pragma unroll
        for (int fm = 0; fm < 4; fm++) {
#pragma unroll
            for (int h = 0; h < 2; h++) {
                float v0 = acc[fm][fn][h * 2 + 0] + bv.x;
                float v1 = acc[fm][fn][h * 2 + 1] + bv.y;
                if (GELU) {
                    const int prow = pbase + m0 + mrow + fm * 16 + grp + h * 8;
                    v0 = 0.5f * v0 * (1.0f + erff(v0 * 0.7071067811865476f));
                    v1 = 0.5f * v1 * (1.0f + erff(v1 * 0.7071067811865476f));
                    *reinterpret_cast<__half2*>(g_Hh + (size_t)prow * NTOT + col) =
                        __floats2half2_rn(v0, v1);
                } else {
                    const int tok = toks[fm][h];
                    if (tok >= 0) {
                        const float2 xr = *reinterpret_cast<const float2*>(
                            xres + (size_t)tok * NTOT + col);
                        *reinterpret_cast<float2*>(outp + (size_t)tok * NTOT + col) =
                            make_float2(v0 + xr.x, v1 + xr.y);
                    }
                }
            }
        }
    }
#undef LOAD_STAGE
}

// ---------------- losses + state reset for next call ----------------
__global__ void finalize_kernel(float* __restrict__ out, int out_size) {
    if (threadIdx.x == 0) {
        long long base = (long long)T_ * H_;
        if ((long long)out_size >= base + 2) {
            float s = 0.f;
            for (int e = 0; e < E_; e++) {
                float p = g_prob_sum[e] / (float)T_;
                s += p * p;
            }
            out[base] = (float)E_ * s;
            out[base + 1] = g_entropy_sum / (float)T_;
        }
        if ((long long)out_size >= base + 2 + E_) {
            for (int e = 0; e < E_; e++)
                out[base + 2 + e] = (float)g_counts[e];
        }
        for (int e = 0; e < E_; e++) { g_counts[e] = 0; g_prob_sum[e] = 0.f; }
        g_entropy_sum = 0.f;
        g_flag = 0;
        g_rdone = 0;
    }
}

// ---------------- launch ----------------
extern "C" void kernel_launch(void* const* d_in, const int* in_sizes, int n_in,
                              void* d_out, int out_size) {
    const float* x  = (const float*)d_in[0];
    const float* Wr = (const float*)d_in[1];
    const float* br = (const float*)d_in[2];
    const float* W1 = (const float*)d_in[3];
    const float* b1 = (const float*)d_in[4];
    const float* W2 = (const float*)d_in[5];
    const float* b2 = (const float*)d_in[6];
    float* out = (float*)d_out;

    cudaFuncSetAttribute(moe_gemm<H_, D_, true>,
                         cudaFuncAttributeMaxDynamicSharedMemorySize, GEMM_SMEM);
    cudaFuncSetAttribute(moe_gemm<D_, H_, false>,
                         cudaFuncAttributeMaxDynamicSharedMemorySize, GEMM_SMEM);

    fused_prep<<<NROUTE + NSCAT + NCONV, 1024>>>(x, Wr, br, W1, W2);   // idx 0
    gather_kernel<<<TPAD_, 128>>>(x);                                   // idx 1
    moe_gemm<H_, D_, true ><<<dim3(D_ / 128, T_ / 128, E_), 256, GEMM_SMEM>>>(x, b1, out); // idx 2
    // idx 3 — the slot ncu captures:
    moe_gemm<D_, H_, false><<<dim3(H_ / 128, T_ / 128, E_), 256, GEMM_SMEM>>>(x, b2, out); // idx 3
    finalize_kernel<<<1, 32>>>(out, out_size);                          // idx 4
}